// round 11
// baseline (speedup 1.0000x reference)
#include <cuda_runtime.h>
#include <cstdint>

#define HIDDEN 1024
#define HEADS  16
#define DKH    64
#define BB     2
#define NN     2048
#define ROWS   (BB*NN)

__device__ float g_Q[ROWS * HIDDEN];
__device__ float g_K[ROWS * HIDDEN];
__device__ float g_V[ROWS * HIDDEN];
__device__ float g_C[ROWS * HIDDEN];
// transposed + bf16-split weights: [4 mats][1024 n-rows][512 k-pairs] u32
__device__ uint32_t g_Wth[4u * 1024u * 512u];
__device__ uint32_t g_Wtl[4u * 1024u * 512u];

__device__ __forceinline__ uint32_t f2tf(float x) {
    uint32_t u; asm("cvt.rna.tf32.f32 %0, %1;" : "=r"(u) : "f"(x)); return u;
}
__device__ __forceinline__ uint32_t pk(float a, float b) {
    uint32_t r; asm("cvt.rn.bf16x2.f32 %0, %1, %2;" : "=r"(r) : "f"(b), "f"(a)); return r;
}
__device__ __forceinline__ float blo(uint32_t u) { return __uint_as_float(u << 16); }
__device__ __forceinline__ float bhi(uint32_t u) { return __uint_as_float(u & 0xffff0000u); }
__device__ __forceinline__ void sp(float f0, float f1, uint32_t& h, uint32_t& l) {
    h = pk(f0, f1);
    l = pk(f0 - blo(h), f1 - bhi(h));
}
__device__ __forceinline__ void mma8(float* d, uint32_t a0, uint32_t a1,
    uint32_t a2, uint32_t a3, uint32_t b0, uint32_t b1) {
    asm volatile("mma.sync.aligned.m16n8k8.row.col.f32.tf32.tf32.f32 "
        "{%0,%1,%2,%3},{%4,%5,%6,%7},{%8,%9},{%0,%1,%2,%3};"
        : "+f"(d[0]), "+f"(d[1]), "+f"(d[2]), "+f"(d[3])
        : "r"(a0), "r"(a1), "r"(a2), "r"(a3), "r"(b0), "r"(b1));
}
__device__ __forceinline__ void mma16(float* d, uint32_t a0, uint32_t a1,
    uint32_t a2, uint32_t a3, uint32_t b0, uint32_t b1) {
    asm volatile("mma.sync.aligned.m16n8k16.row.col.f32.bf16.bf16.f32 "
        "{%0,%1,%2,%3},{%4,%5,%6,%7},{%8,%9},{%0,%1,%2,%3};"
        : "+f"(d[0]), "+f"(d[1]), "+f"(d[2]), "+f"(d[3])
        : "r"(a0), "r"(a1), "r"(a2), "r"(a3), "r"(b0), "r"(b1));
}

// ---------------------------------------------------------------------------
// One-shot: transpose W [k][n] -> [n][k] and split to bf16 h/l pair arrays.
// pair low half = even k (matches mma16 A/B fragment convention used below).
// ---------------------------------------------------------------------------
__global__ void transpose_split_kernel(
    const float* __restrict__ W0, const float* __restrict__ W1,
    const float* __restrict__ W2, const float* __restrict__ W3,
    uint32_t* __restrict__ outH, uint32_t* __restrict__ outL)
{
    __shared__ float ts[32][33];
    const float* W = (blockIdx.z == 0) ? W0 : (blockIdx.z == 1) ? W1
                   : (blockIdx.z == 2) ? W2 : W3;
    uint32_t* oh = outH + (size_t)blockIdx.z * 524288u;
    uint32_t* ol = outL + (size_t)blockIdx.z * 524288u;
    const int k0 = blockIdx.y * 32, n0 = blockIdx.x * 32;
    const int tx = threadIdx.x, ty = threadIdx.y;    // (32, 8)
#pragma unroll
    for (int i = 0; i < 4; i++)
        ts[ty + i * 8][tx] = W[(size_t)(k0 + ty + i * 8) * 1024 + n0 + tx];
    __syncthreads();
    if (tx < 16) {
#pragma unroll
        for (int i = 0; i < 4; i++) {
            int n = ty + i * 8;
            uint32_t h, l;
            sp(ts[2 * tx][n], ts[2 * tx + 1][n], h, l);
            size_t idx = (size_t)(n0 + n) * 512 + (k0 >> 1) + tx;
            oh[idx] = h; ol[idx] = l;
        }
    }
}

// ---------------------------------------------------------------------------
// bf16x3 GEMM, BK=32, pre-split W, double-buffered dynamic smem.
// smem per stage: Ah/Al/Wh/Wl each [128 rows][20 u32] (16 kpairs + 4 pad).
// Frag loads conflict-free; staging is STS.128 conflict-free. 2 CTA/SM.
// ---------------------------------------------------------------------------
#define GSTG (128 * 20)                 // u32 per array
#define GSM_BYTES (2 * 4 * GSTG * 4)    // 81920 B

__global__ void __launch_bounds__(256, 2) gemm_ps_kernel(
    const float* __restrict__ A,
    const uint32_t* __restrict__ Wh2, const uint32_t* __restrict__ Wl2,
    const float* __restrict__ bias, float* __restrict__ C)
{
    extern __shared__ uint32_t gsm[];
    const int tid = threadIdx.x, lane = tid & 31, wid = tid >> 5;
    const int g = lane >> 2, t = lane & 3;
    const int wm = (wid & 3) * 32, wn = (wid >> 2) * 64;
    const int bn = blockIdx.x, bm = blockIdx.y;

    const float* Ab = A + (size_t)(bm * 128) * 1024;
    const uint32_t* Whb = Wh2 + (size_t)(bn * 128) * 512;
    const uint32_t* Wlb = Wl2 + (size_t)(bn * 128) * 512;

    float acc[2][8][4];
#pragma unroll
    for (int mi = 0; mi < 2; mi++)
#pragma unroll
        for (int n = 0; n < 8; n++)
#pragma unroll
            for (int j = 0; j < 4; j++) acc[mi][n][j] = 0.f;

    const int row  = tid >> 1;          // 0..127 (A-row and W-row loader)
    const int half = tid & 1;           // k-half within BK=32
    const int kp0  = half * 8;          // kpair base within iter (0 or 8)

    float4 av[4];
    uint4 wh[2], wl[2];
#define G_LOAD(it) do { \
    _Pragma("unroll") for (int j = 0; j < 4; j++) \
        av[j] = *(const float4*)(Ab + (size_t)row * 1024 + (it) * 32 + half * 16 + j * 4); \
    wh[0] = *(const uint4*)(Whb + (size_t)row * 512 + (it) * 16 + kp0); \
    wh[1] = *(const uint4*)(Whb + (size_t)row * 512 + (it) * 16 + kp0 + 4); \
    wl[0] = *(const uint4*)(Wlb + (size_t)row * 512 + (it) * 16 + kp0); \
    wl[1] = *(const uint4*)(Wlb + (size_t)row * 512 + (it) * 16 + kp0 + 4); \
} while (0)
#define G_STS(pb) do { \
    uint32_t* Ah_ = gsm + (pb) * 4 * GSTG; \
    uint32_t* Al_ = Ah_ + GSTG; \
    uint32_t* Wh_ = Al_ + GSTG; \
    uint32_t* Wl_ = Wh_ + GSTG; \
    uint4 hA0, lA0, hA1, lA1; \
    sp(av[0].x, av[0].y, hA0.x, lA0.x); sp(av[0].z, av[0].w, hA0.y, lA0.y); \
    sp(av[1].x, av[1].y, hA0.z, lA0.z); sp(av[1].z, av[1].w, hA0.w, lA0.w); \
    sp(av[2].x, av[2].y, hA1.x, lA1.x); sp(av[2].z, av[2].w, hA1.y, lA1.y); \
    sp(av[3].x, av[3].y, hA1.z, lA1.z); sp(av[3].z, av[3].w, hA1.w, lA1.w); \
    uint32_t* ad = Ah_ + row * 20 + kp0; \
    *(uint4*)ad = hA0;  *(uint4*)(ad + 4) = hA1; \
    uint32_t* al_ = Al_ + row * 20 + kp0; \
    *(uint4*)al_ = lA0; *(uint4*)(al_ + 4) = lA1; \
    uint32_t* wd = Wh_ + row * 20 + kp0; \
    *(uint4*)wd = wh[0]; *(uint4*)(wd + 4) = wh[1]; \
    uint32_t* wld = Wl_ + row * 20 + kp0; \
    *(uint4*)wld = wl[0]; *(uint4*)(wld + 4) = wl[1]; \
} while (0)

    G_LOAD(0);
    G_STS(0);
    __syncthreads();
    int p = 0;

    for (int it = 0; it < 32; it++) {
        if (it + 1 < 32) G_LOAD(it + 1);

        uint32_t* Ah_ = gsm + p * 4 * GSTG;
        uint32_t* Al_ = Ah_ + GSTG;
        uint32_t* Wh_ = Al_ + GSTG;
        uint32_t* Wl_ = Wh_ + GSTG;

#pragma unroll
        for (int ks = 0; ks < 2; ks++) {
            const int kb = ks * 8;
            uint32_t afh[2][4], afl[2][4];
#pragma unroll
            for (int mi = 0; mi < 2; mi++) {
                const int r0 = (wm + mi * 16 + g) * 20;
                const int r1 = (wm + mi * 16 + g + 8) * 20;
                afh[mi][0] = Ah_[r0 + kb + t];     afh[mi][1] = Ah_[r1 + kb + t];
                afh[mi][2] = Ah_[r0 + kb + t + 4]; afh[mi][3] = Ah_[r1 + kb + t + 4];
                afl[mi][0] = Al_[r0 + kb + t];     afl[mi][1] = Al_[r1 + kb + t];
                afl[mi][2] = Al_[r0 + kb + t + 4]; afl[mi][3] = Al_[r1 + kb + t + 4];
            }
#pragma unroll
            for (int n = 0; n < 8; n++) {
                const int wr = (wn + n * 8 + g) * 20;
                uint32_t b0h = Wh_[wr + kb + t], b1h = Wh_[wr + kb + t + 4];
                uint32_t b0l = Wl_[wr + kb + t], b1l = Wl_[wr + kb + t + 4];
#pragma unroll
                for (int mi = 0; mi < 2; mi++) {
                    mma16(acc[mi][n], afh[mi][0], afh[mi][1], afh[mi][2], afh[mi][3], b0h, b1h);
                    mma16(acc[mi][n], afl[mi][0], afl[mi][1], afl[mi][2], afl[mi][3], b0h, b1h);
                    mma16(acc[mi][n], afh[mi][0], afh[mi][1], afh[mi][2], afh[mi][3], b0l, b1l);
                }
            }
        }
        if (it + 1 < 32) G_STS(p ^ 1);
        __syncthreads();
        p ^= 1;
    }

#pragma unroll
    for (int mi = 0; mi < 2; mi++) {
        int row0 = bm * 128 + wm + mi * 16 + g;
#pragma unroll
        for (int n = 0; n < 8; n++) {
            int col = bn * 128 + wn + n * 8 + 2 * t;
            float2 bv = *(const float2*)(bias + col);
            *(float2*)(C + (size_t)row0 * 1024 + col) =
                make_float2(acc[mi][n][0] + bv.x, acc[mi][n][1] + bv.y);
            *(float2*)(C + (size_t)(row0 + 8) * 1024 + col) =
                make_float2(acc[mi][n][2] + bv.x, acc[mi][n][3] + bv.y);
        }
    }
}

// ---------------------------------------------------------------------------
// Flash (round-9 verbatim, measured 473us): Br=128, Bc=64, launch_bounds(256,2).
// ---------------------------------------------------------------------------
__global__ void __launch_bounds__(256, 2) flash_kernel(
    const float* __restrict__ bias, const float* __restrict__ mask,
    float* __restrict__ ctx)
{
    __shared__ uint32_t Kp[64 * 72];
    __shared__ uint32_t Vhl[32 * 136];

    const int tid = threadIdx.x, lane = tid & 31, wid = tid >> 5;
    const int g = lane >> 2, t = lane & 3;
    const int wrow = wid * 16;
    const int h = blockIdx.x, q0 = blockIdx.y * 128, b = blockIdx.z;

    const float* Qg = g_Q + ((size_t)b * NN + q0) * HIDDEN + h * DKH;
    const float* Kg = g_K + (size_t)b * NN * HIDDEN + h * DKH;
    const float* Vg = g_V + (size_t)b * NN * HIDDEN + h * DKH;

    const float L2E = 1.44269504088896340736f;
    const float QSC = 0.125f * L2E;

    uint32_t qa[8][4];
#pragma unroll
    for (int kb = 0; kb < 8; kb++) {
        qa[kb][0] = f2tf(__ldg(Qg + (size_t)(wrow+g)  *HIDDEN + kb*8 + t)   * QSC);
        qa[kb][1] = f2tf(__ldg(Qg + (size_t)(wrow+g+8)*HIDDEN + kb*8 + t)   * QSC);
        qa[kb][2] = f2tf(__ldg(Qg + (size_t)(wrow+g)  *HIDDEN + kb*8 + t+4) * QSC);
        qa[kb][3] = f2tf(__ldg(Qg + (size_t)(wrow+g+8)*HIDDEN + kb*8 + t+4) * QSC);
    }

    float Oa[8][4];
#pragma unroll
    for (int n = 0; n < 8; n++)
#pragma unroll
        for (int j = 0; j < 4; j++) Oa[n][j] = 0.f;
    float m0 = -1e30f, m1 = -1e30f, l0 = 0.f, l1 = 0.f;

    const float* biasB = bias + ((size_t)b * NN + q0 + wrow) * NN;
    const float* maskB = mask + ((size_t)b * NN + q0 + wrow) * NN;

    const int kkey = tid >> 3, kkb = tid & 7;
    const int vrp  = tid >> 4, vdq = tid & 15;

    for (int kt = 0; kt < NN / 64; kt++) {
        const int k0 = kt * 64;
        __syncthreads();

#pragma unroll
        for (int i = 0; i < 2; i++) {
            int key = kkey + i * 32;
            const float* kr = Kg + (size_t)(k0 + key) * HIDDEN + kkb * 8;
            float4 fa = *(const float4*)kr;
            float4 fb = *(const float4*)(kr + 4);
            uint32_t* d = &Kp[key * 72 + kkb * 8];
            *(uint4*)d       = make_uint4(f2tf(fa.x), f2tf(fb.x), f2tf(fa.y), f2tf(fb.y));
            *(uint4*)(d + 4) = make_uint4(f2tf(fa.z), f2tf(fb.z), f2tf(fa.w), f2tf(fb.w));
        }
#pragma unroll
        for (int i = 0; i < 2; i++) {
            int rp = vrp + i * 16;
            const float* vr = Vg + (size_t)(k0 + 2 * rp) * HIDDEN + vdq * 4;
            float4 f0 = *(const float4*)vr;
            float4 f1 = *(const float4*)(vr + HIDDEN);
            uint4 u0, u1;
            sp(f0.x, f1.x, u0.x, u0.y); sp(f0.y, f1.y, u0.z, u0.w);
            sp(f0.z, f1.z, u1.x, u1.y); sp(f0.w, f1.w, u1.z, u1.w);
            uint32_t* d = &Vhl[rp * 136 + vdq * 8];
            *(uint4*)d       = u0;
            *(uint4*)(d + 4) = u1;
        }
        __syncthreads();

        float sacc[8][4];
#pragma unroll
        for (int n = 0; n < 8; n++)
#pragma unroll
            for (int j = 0; j < 4; j++) sacc[n][j] = 0.f;
#pragma unroll
        for (int kb = 0; kb < 8; kb++)
#pragma unroll
            for (int n = 0; n < 8; n++) {
                uint2 bb = *(const uint2*)&Kp[(n*8+g) * 72 + kb*8 + 2*t];
                mma8(sacc[n], qa[kb][0], qa[kb][1], qa[kb][2], qa[kb][3], bb.x, bb.y);
            }

        float mx0 = -1e30f, mx1 = -1e30f;
#pragma unroll
        for (int n = 0; n < 8; n++) {
            float2 u  = __ldg((const float2*)(biasB + (size_t)g    * NN + k0 + n*8 + 2*t));
            float2 um = __ldg((const float2*)(maskB + (size_t)g    * NN + k0 + n*8 + 2*t));
            float2 w  = __ldg((const float2*)(biasB + (size_t)(g+8)* NN + k0 + n*8 + 2*t));
            float2 wm = __ldg((const float2*)(maskB + (size_t)(g+8)* NN + k0 + n*8 + 2*t));
            sacc[n][0] += (u.x + um.x) * L2E;
            sacc[n][1] += (u.y + um.y) * L2E;
            sacc[n][2] += (w.x + wm.x) * L2E;
            sacc[n][3] += (w.y + wm.y) * L2E;
            mx0 = fmaxf(mx0, fmaxf(sacc[n][0], sacc[n][1]));
            mx1 = fmaxf(mx1, fmaxf(sacc[n][2], sacc[n][3]));
        }
        mx0 = fmaxf(mx0, __shfl_xor_sync(~0u, mx0, 1));
        mx0 = fmaxf(mx0, __shfl_xor_sync(~0u, mx0, 2));
        mx1 = fmaxf(mx1, __shfl_xor_sync(~0u, mx1, 1));
        mx1 = fmaxf(mx1, __shfl_xor_sync(~0u, mx1, 2));
        float mn0 = fmaxf(m0, mx0), mn1 = fmaxf(m1, mx1);
        float c0 = exp2f(m0 - mn0), c1 = exp2f(m1 - mn1);
        float rs0 = 0.f, rs1 = 0.f;
#pragma unroll
        for (int n = 0; n < 8; n++) {
            sacc[n][0] = exp2f(sacc[n][0] - mn0);
            sacc[n][1] = exp2f(sacc[n][1] - mn0);
            sacc[n][2] = exp2f(sacc[n][2] - mn1);
            sacc[n][3] = exp2f(sacc[n][3] - mn1);
            rs0 += sacc[n][0] + sacc[n][1];
            rs1 += sacc[n][2] + sacc[n][3];
        }
        rs0 += __shfl_xor_sync(~0u, rs0, 1); rs0 += __shfl_xor_sync(~0u, rs0, 2);
        rs1 += __shfl_xor_sync(~0u, rs1, 1); rs1 += __shfl_xor_sync(~0u, rs1, 2);
        l0 = l0 * c0 + rs0; l1 = l1 * c1 + rs1;
        m0 = mn0; m1 = mn1;
#pragma unroll
        for (int n = 0; n < 8; n++) {
            Oa[n][0] *= c0; Oa[n][1] *= c0;
            Oa[n][2] *= c1; Oa[n][3] *= c1;
        }

#pragma unroll
        for (int kb = 0; kb < 4; kb++) {
            uint32_t a0h, a0l, a1h, a1l, a2h, a2l, a3h, a3l;
            sp(sacc[2*kb][0],   sacc[2*kb][1],   a0h, a0l);
            sp(sacc[2*kb][2],   sacc[2*kb][3],   a1h, a1l);
            sp(sacc[2*kb+1][0], sacc[2*kb+1][1], a2h, a2l);
            sp(sacc[2*kb+1][2], sacc[2*kb+1][3], a3h, a3l);
#pragma unroll
            for (int n = 0; n < 8; n++) {
                uint2 p0 = *(const uint2*)&Vhl[(kb*8+t)   * 136 + (n*8+g) * 2];
                uint2 p1 = *(const uint2*)&Vhl[(kb*8+t+4) * 136 + (n*8+g) * 2];
                mma16(Oa[n], a0h, a1h, a2h, a3h, p0.x, p1.x);
                mma16(Oa[n], a0l, a1l, a2l, a3l, p0.x, p1.x);
                mma16(Oa[n], a0h, a1h, a2h, a3h, p0.y, p1.y);
            }
        }
    }

    float inv0 = 1.f / l0, inv1 = 1.f / l1;
    float* o0 = ctx + ((size_t)b * NN + q0 + wrow + g) * HIDDEN + h * DKH;
    float* o1 = o0 + (size_t)8 * HIDDEN;
#pragma unroll
    for (int n = 0; n < 8; n++) {
        *(float2*)&o0[n*8 + 2*t] = make_float2(Oa[n][0]*inv0, Oa[n][1]*inv0);
        *(float2*)&o1[n*8 + 2*t] = make_float2(Oa[n][2]*inv1, Oa[n][3]*inv1);
    }
}

extern "C" void kernel_launch(void* const* d_in, const int* in_sizes, int n_in,
                              void* d_out, int out_size)
{
    const float* q    = (const float*)d_in[0];
    const float* k    = (const float*)d_in[1];
    const float* v    = (const float*)d_in[2];
    const float* abia = (const float*)d_in[3];
    const float* amask= (const float*)d_in[4];
    const float* Wq   = (const float*)d_in[5];
    const float* bq   = (const float*)d_in[6];
    const float* Wk   = (const float*)d_in[7];
    const float* bk   = (const float*)d_in[8];
    const float* Wv   = (const float*)d_in[9];
    const float* bv   = (const float*)d_in[10];
    const float* Wo   = (const float*)d_in[11];
    const float* bo   = (const float*)d_in[12];
    float* out = (float*)d_out;

    float *Qp, *Kp_, *Vp, *Cp;
    uint32_t *WH, *WL;
    cudaGetSymbolAddress((void**)&Qp, g_Q);
    cudaGetSymbolAddress((void**)&Kp_, g_K);
    cudaGetSymbolAddress((void**)&Vp, g_V);
    cudaGetSymbolAddress((void**)&Cp, g_C);
    cudaGetSymbolAddress((void**)&WH, g_Wth);
    cudaGetSymbolAddress((void**)&WL, g_Wtl);

    cudaFuncSetAttribute(gemm_ps_kernel,
                         cudaFuncAttributeMaxDynamicSharedMemorySize, GSM_BYTES);

    transpose_split_kernel<<<dim3(32, 32, 4), dim3(32, 8)>>>(Wq, Wk, Wv, Wo, WH, WL);

    dim3 gb(HIDDEN / 128, ROWS / 128);     // (8, 32)
    gemm_ps_kernel<<<gb, 256, GSM_BYTES>>>(q, WH,            WL,            bq, Qp);
    gemm_ps_kernel<<<gb, 256, GSM_BYTES>>>(k, WH + 524288u,  WL + 524288u,  bk, Kp_);
    gemm_ps_kernel<<<gb, 256, GSM_BYTES>>>(v, WH + 1048576u, WL + 1048576u, bv, Vp);

    dim3 gf(HEADS, NN / 128, BB);          // (16, 16, 2)
    flash_kernel<<<gf, 256>>>(abia, amask, Cp);

    gemm_ps_kernel<<<gb, 256, GSM_BYTES>>>(Cp, WH + 1572864u, WL + 1572864u, bo, out);
}

// round 12
// speedup vs baseline: 1.1822x; 1.1822x over previous
#include <cuda_runtime.h>
#include <cstdint>

#define HIDDEN 1024
#define HEADS  16
#define DKH    64
#define BB     2
#define NN     2048
#define ROWS   (BB*NN)

__device__ float g_Q[ROWS * HIDDEN];
__device__ float g_K[ROWS * HIDDEN];
__device__ float g_V[ROWS * HIDDEN];
__device__ float g_C[ROWS * HIDDEN];
// K-major bf16-split weights: [4 mats][512 kpairs][1024 n] u32 (h and l)
__device__ uint32_t g_Wh[4u * 512u * 1024u];
__device__ uint32_t g_Wl[4u * 512u * 1024u];

__device__ __forceinline__ uint32_t f2tf(float x) {
    uint32_t u; asm("cvt.rna.tf32.f32 %0, %1;" : "=r"(u) : "f"(x)); return u;
}
__device__ __forceinline__ uint32_t pk(float a, float b) {
    uint32_t r; asm("cvt.rn.bf16x2.f32 %0, %1, %2;" : "=r"(r) : "f"(b), "f"(a)); return r;
}
__device__ __forceinline__ float blo(uint32_t u) { return __uint_as_float(u << 16); }
__device__ __forceinline__ float bhi(uint32_t u) { return __uint_as_float(u & 0xffff0000u); }
__device__ __forceinline__ void sp(float f0, float f1, uint32_t& h, uint32_t& l) {
    h = pk(f0, f1);
    l = pk(f0 - blo(h), f1 - bhi(h));
}
__device__ __forceinline__ void mma8(float* d, uint32_t a0, uint32_t a1,
    uint32_t a2, uint32_t a3, uint32_t b0, uint32_t b1) {
    asm volatile("mma.sync.aligned.m16n8k8.row.col.f32.tf32.tf32.f32 "
        "{%0,%1,%2,%3},{%4,%5,%6,%7},{%8,%9},{%0,%1,%2,%3};"
        : "+f"(d[0]), "+f"(d[1]), "+f"(d[2]), "+f"(d[3])
        : "r"(a0), "r"(a1), "r"(a2), "r"(a3), "r"(b0), "r"(b1));
}
__device__ __forceinline__ void mma16(float* d, uint32_t a0, uint32_t a1,
    uint32_t a2, uint32_t a3, uint32_t b0, uint32_t b1) {
    asm volatile("mma.sync.aligned.m16n8k16.row.col.f32.bf16.bf16.f32 "
        "{%0,%1,%2,%3},{%4,%5,%6,%7},{%8,%9},{%0,%1,%2,%3};"
        : "+f"(d[0]), "+f"(d[1]), "+f"(d[2]), "+f"(d[3])
        : "r"(a0), "r"(a1), "r"(a2), "r"(a3), "r"(b0), "r"(b1));
}

// ---------------------------------------------------------------------------
// One-shot: split W (K-major kept!) into bf16 (h,l) pair arrays.
// W'[kp][n] pairs W[2kp][n] (low half) with W[2kp+1][n] (high half).
// Fully coalesced read and write (n contiguous).
// ---------------------------------------------------------------------------
__global__ void split_w_kernel(
    const float* __restrict__ W0, const float* __restrict__ W1,
    const float* __restrict__ W2, const float* __restrict__ W3,
    uint32_t* __restrict__ outH, uint32_t* __restrict__ outL)
{
    const float* W = (blockIdx.y == 0) ? W0 : (blockIdx.y == 1) ? W1
                   : (blockIdx.y == 2) ? W2 : W3;
    uint32_t* oh = outH + (size_t)blockIdx.y * 524288u;
    uint32_t* ol = outL + (size_t)blockIdx.y * 524288u;
    int idx = blockIdx.x * 256 + threadIdx.x;      // 0 .. 524287
    int kp = idx >> 10, n = idx & 1023;
    float w0 = W[(size_t)(2 * kp) * 1024 + n];
    float w1 = W[(size_t)(2 * kp + 1) * 1024 + n];
    uint32_t h, l;
    sp(w0, w1, h, l);
    oh[idx] = h; ol[idx] = l;
}

// ---------------------------------------------------------------------------
// bf16x3 GEMM — round-6/9 structure exactly, but W read pre-split (K-major,
// same coalesced pattern as before; W-split ALU removed from hot loop).
// BM=BN=128, BK=16, double-buffered, 2 CTA/SM.
// ---------------------------------------------------------------------------
__global__ void __launch_bounds__(256, 2) gemm_bf3_kernel(
    const float* __restrict__ A,
    const uint32_t* __restrict__ WhG, const uint32_t* __restrict__ WlG,
    const float* __restrict__ bias, float* __restrict__ C)
{
    __shared__ uint32_t Ah[2][8][136], Al[2][8][136], Wh[2][8][136], Wl[2][8][136];
    const int tid = threadIdx.x, lane = tid & 31, wid = tid >> 5;
    const int g = lane >> 2, t = lane & 3;
    const int wm = (wid & 3) * 32, wn = (wid >> 2) * 64;
    const float* Ab = A + (size_t)blockIdx.y * 128 * 1024;
    const uint32_t* WhB = WhG + blockIdx.x * 128;   // [kpair][1024 n]
    const uint32_t* WlB = WlG + blockIdx.x * 128;

    float acc[2][8][4];
#pragma unroll
    for (int mi = 0; mi < 2; mi++)
#pragma unroll
        for (int n = 0; n < 8; n++)
#pragma unroll
            for (int j = 0; j < 4; j++) acc[mi][n][j] = 0.f;

    const int arow = tid >> 2, ac4 = tid & 3;   // A rows arow, arow+64
    const int kp = tid >> 5, c4 = tid & 31;     // W kpair kp, cols c4*4..+3

    float4 ra0, ra1;
    uint4 rwh, rwl;
#define G_LOAD(k0) do { \
    ra0 = *(const float4*)(Ab + (size_t)arow * 1024 + (k0) + ac4 * 4); \
    ra1 = *(const float4*)(Ab + (size_t)(arow + 64) * 1024 + (k0) + ac4 * 4); \
    rwh = *(const uint4*)(WhB + (size_t)(((k0) >> 1) + kp) * 1024 + c4 * 4); \
    rwl = *(const uint4*)(WlB + (size_t)(((k0) >> 1) + kp) * 1024 + c4 * 4); \
} while (0)
#define G_STS(pb) do { \
    uint32_t h_, l_; \
    sp(ra0.x, ra0.y, h_, l_); Ah[pb][2*ac4][arow] = h_;      Al[pb][2*ac4][arow] = l_; \
    sp(ra0.z, ra0.w, h_, l_); Ah[pb][2*ac4+1][arow] = h_;    Al[pb][2*ac4+1][arow] = l_; \
    sp(ra1.x, ra1.y, h_, l_); Ah[pb][2*ac4][arow+64] = h_;   Al[pb][2*ac4][arow+64] = l_; \
    sp(ra1.z, ra1.w, h_, l_); Ah[pb][2*ac4+1][arow+64] = h_; Al[pb][2*ac4+1][arow+64] = l_; \
    *(uint4*)&Wh[pb][kp][c4 * 4] = rwh; \
    *(uint4*)&Wl[pb][kp][c4 * 4] = rwl; \
} while (0)

    G_LOAD(0);
    G_STS(0);
    __syncthreads();
    int p = 0;

    for (int k0 = 0; k0 < 1024; k0 += 16) {
        if (k0 + 16 < 1024) G_LOAD(k0 + 16);

        uint32_t af[2][8];
#pragma unroll
        for (int mi = 0; mi < 2; mi++) {
            int mb = wm + mi * 16;
            af[mi][0] = Ah[p][t][mb+g];   af[mi][1] = Ah[p][t][mb+g+8];
            af[mi][2] = Ah[p][t+4][mb+g]; af[mi][3] = Ah[p][t+4][mb+g+8];
            af[mi][4] = Al[p][t][mb+g];   af[mi][5] = Al[p][t][mb+g+8];
            af[mi][6] = Al[p][t+4][mb+g]; af[mi][7] = Al[p][t+4][mb+g+8];
        }
#pragma unroll
        for (int n = 0; n < 8; n++) {
            uint32_t b0h = Wh[p][t][wn+n*8+g], b1h = Wh[p][t+4][wn+n*8+g];
            uint32_t b0l = Wl[p][t][wn+n*8+g], b1l = Wl[p][t+4][wn+n*8+g];
#pragma unroll
            for (int mi = 0; mi < 2; mi++) {
                mma16(acc[mi][n], af[mi][0], af[mi][1], af[mi][2], af[mi][3], b0h, b1h);
                mma16(acc[mi][n], af[mi][4], af[mi][5], af[mi][6], af[mi][7], b0h, b1h);
                mma16(acc[mi][n], af[mi][0], af[mi][1], af[mi][2], af[mi][3], b0l, b1l);
            }
        }
        if (k0 + 16 < 1024) G_STS(p ^ 1);
        __syncthreads();
        p ^= 1;
    }

#pragma unroll
    for (int mi = 0; mi < 2; mi++) {
        int row0 = blockIdx.y * 128 + wm + mi * 16 + g;
#pragma unroll
        for (int n = 0; n < 8; n++) {
            int col = blockIdx.x * 128 + wn + n * 8 + 2 * t;
            float2 bv = *(const float2*)(bias + col);
            *(float2*)(C + (size_t)row0 * 1024 + col) =
                make_float2(acc[mi][n][0] + bv.x, acc[mi][n][1] + bv.y);
            *(float2*)(C + (size_t)(row0 + 8) * 1024 + col) =
                make_float2(acc[mi][n][2] + bv.x, acc[mi][n][3] + bv.y);
        }
    }
}

// ---------------------------------------------------------------------------
// Flash (round-9 verbatim, measured 473 us).
// ---------------------------------------------------------------------------
__global__ void __launch_bounds__(256, 2) flash_kernel(
    const float* __restrict__ bias, const float* __restrict__ mask,
    float* __restrict__ ctx)
{
    __shared__ uint32_t Kp[64 * 72];
    __shared__ uint32_t Vhl[32 * 136];

    const int tid = threadIdx.x, lane = tid & 31, wid = tid >> 5;
    const int g = lane >> 2, t = lane & 3;
    const int wrow = wid * 16;
    const int h = blockIdx.x, q0 = blockIdx.y * 128, b = blockIdx.z;

    const float* Qg = g_Q + ((size_t)b * NN + q0) * HIDDEN + h * DKH;
    const float* Kg = g_K + (size_t)b * NN * HIDDEN + h * DKH;
    const float* Vg = g_V + (size_t)b * NN * HIDDEN + h * DKH;

    const float L2E = 1.44269504088896340736f;
    const float QSC = 0.125f * L2E;

    uint32_t qa[8][4];
#pragma unroll
    for (int kb = 0; kb < 8; kb++) {
        qa[kb][0] = f2tf(__ldg(Qg + (size_t)(wrow+g)  *HIDDEN + kb*8 + t)   * QSC);
        qa[kb][1] = f2tf(__ldg(Qg + (size_t)(wrow+g+8)*HIDDEN + kb*8 + t)   * QSC);
        qa[kb][2] = f2tf(__ldg(Qg + (size_t)(wrow+g)  *HIDDEN + kb*8 + t+4) * QSC);
        qa[kb][3] = f2tf(__ldg(Qg + (size_t)(wrow+g+8)*HIDDEN + kb*8 + t+4) * QSC);
    }

    float Oa[8][4];
#pragma unroll
    for (int n = 0; n < 8; n++)
#pragma unroll
        for (int j = 0; j < 4; j++) Oa[n][j] = 0.f;
    float m0 = -1e30f, m1 = -1e30f, l0 = 0.f, l1 = 0.f;

    const float* biasB = bias + ((size_t)b * NN + q0 + wrow) * NN;
    const float* maskB = mask + ((size_t)b * NN + q0 + wrow) * NN;

    const int kkey = tid >> 3, kkb = tid & 7;
    const int vrp  = tid >> 4, vdq = tid & 15;

    for (int kt = 0; kt < NN / 64; kt++) {
        const int k0 = kt * 64;
        __syncthreads();

#pragma unroll
        for (int i = 0; i < 2; i++) {
            int key = kkey + i * 32;
            const float* kr = Kg + (size_t)(k0 + key) * HIDDEN + kkb * 8;
            float4 fa = *(const float4*)kr;
            float4 fb = *(const float4*)(kr + 4);
            uint32_t* d = &Kp[key * 72 + kkb * 8];
            *(uint4*)d       = make_uint4(f2tf(fa.x), f2tf(fb.x), f2tf(fa.y), f2tf(fb.y));
            *(uint4*)(d + 4) = make_uint4(f2tf(fa.z), f2tf(fb.z), f2tf(fa.w), f2tf(fb.w));
        }
#pragma unroll
        for (int i = 0; i < 2; i++) {
            int rp = vrp + i * 16;
            const float* vr = Vg + (size_t)(k0 + 2 * rp) * HIDDEN + vdq * 4;
            float4 f0 = *(const float4*)vr;
            float4 f1 = *(const float4*)(vr + HIDDEN);
            uint4 u0, u1;
            sp(f0.x, f1.x, u0.x, u0.y); sp(f0.y, f1.y, u0.z, u0.w);
            sp(f0.z, f1.z, u1.x, u1.y); sp(f0.w, f1.w, u1.z, u1.w);
            uint32_t* d = &Vhl[rp * 136 + vdq * 8];
            *(uint4*)d       = u0;
            *(uint4*)(d + 4) = u1;
        }
        __syncthreads();

        float sacc[8][4];
#pragma unroll
        for (int n = 0; n < 8; n++)
#pragma unroll
            for (int j = 0; j < 4; j++) sacc[n][j] = 0.f;
#pragma unroll
        for (int kb = 0; kb < 8; kb++)
#pragma unroll
            for (int n = 0; n < 8; n++) {
                uint2 bb = *(const uint2*)&Kp[(n*8+g) * 72 + kb*8 + 2*t];
                mma8(sacc[n], qa[kb][0], qa[kb][1], qa[kb][2], qa[kb][3], bb.x, bb.y);
            }

        float mx0 = -1e30f, mx1 = -1e30f;
#pragma unroll
        for (int n = 0; n < 8; n++) {
            float2 u  = __ldg((const float2*)(biasB + (size_t)g    * NN + k0 + n*8 + 2*t));
            float2 um = __ldg((const float2*)(maskB + (size_t)g    * NN + k0 + n*8 + 2*t));
            float2 w  = __ldg((const float2*)(biasB + (size_t)(g+8)* NN + k0 + n*8 + 2*t));
            float2 wm = __ldg((const float2*)(maskB + (size_t)(g+8)* NN + k0 + n*8 + 2*t));
            sacc[n][0] += (u.x + um.x) * L2E;
            sacc[n][1] += (u.y + um.y) * L2E;
            sacc[n][2] += (w.x + wm.x) * L2E;
            sacc[n][3] += (w.y + wm.y) * L2E;
            mx0 = fmaxf(mx0, fmaxf(sacc[n][0], sacc[n][1]));
            mx1 = fmaxf(mx1, fmaxf(sacc[n][2], sacc[n][3]));
        }
        mx0 = fmaxf(mx0, __shfl_xor_sync(~0u, mx0, 1));
        mx0 = fmaxf(mx0, __shfl_xor_sync(~0u, mx0, 2));
        mx1 = fmaxf(mx1, __shfl_xor_sync(~0u, mx1, 1));
        mx1 = fmaxf(mx1, __shfl_xor_sync(~0u, mx1, 2));
        float mn0 = fmaxf(m0, mx0), mn1 = fmaxf(m1, mx1);
        float c0 = exp2f(m0 - mn0), c1 = exp2f(m1 - mn1);
        float rs0 = 0.f, rs1 = 0.f;
#pragma unroll
        for (int n = 0; n < 8; n++) {
            sacc[n][0] = exp2f(sacc[n][0] - mn0);
            sacc[n][1] = exp2f(sacc[n][1] - mn0);
            sacc[n][2] = exp2f(sacc[n][2] - mn1);
            sacc[n][3] = exp2f(sacc[n][3] - mn1);
            rs0 += sacc[n][0] + sacc[n][1];
            rs1 += sacc[n][2] + sacc[n][3];
        }
        rs0 += __shfl_xor_sync(~0u, rs0, 1); rs0 += __shfl_xor_sync(~0u, rs0, 2);
        rs1 += __shfl_xor_sync(~0u, rs1, 1); rs1 += __shfl_xor_sync(~0u, rs1, 2);
        l0 = l0 * c0 + rs0; l1 = l1 * c1 + rs1;
        m0 = mn0; m1 = mn1;
#pragma unroll
        for (int n = 0; n < 8; n++) {
            Oa[n][0] *= c0; Oa[n][1] *= c0;
            Oa[n][2] *= c1; Oa[n][3] *= c1;
        }

#pragma unroll
        for (int kb = 0; kb < 4; kb++) {
            uint32_t a0h, a0l, a1h, a1l, a2h, a2l, a3h, a3l;
            sp(sacc[2*kb][0],   sacc[2*kb][1],   a0h, a0l);
            sp(sacc[2*kb][2],   sacc[2*kb][3],   a1h, a1l);
            sp(sacc[2*kb+1][0], sacc[2*kb+1][1], a2h, a2l);
            sp(sacc[2*kb+1][2], sacc[2*kb+1][3], a3h, a3l);
#pragma unroll
            for (int n = 0; n < 8; n++) {
                uint2 p0 = *(const uint2*)&Vhl[(kb*8+t)   * 136 + (n*8+g) * 2];
                uint2 p1 = *(const uint2*)&Vhl[(kb*8+t+4) * 136 + (n*8+g) * 2];
                mma16(Oa[n], a0h, a1h, a2h, a3h, p0.x, p1.x);
                mma16(Oa[n], a0l, a1l, a2l, a3l, p0.x, p1.x);
                mma16(Oa[n], a0h, a1h, a2h, a3h, p0.y, p1.y);
            }
        }
    }

    float inv0 = 1.f / l0, inv1 = 1.f / l1;
    float* o0 = ctx + ((size_t)b * NN + q0 + wrow + g) * HIDDEN + h * DKH;
    float* o1 = o0 + (size_t)8 * HIDDEN;
#pragma unroll
    for (int n = 0; n < 8; n++) {
        *(float2*)&o0[n*8 + 2*t] = make_float2(Oa[n][0]*inv0, Oa[n][1]*inv0);
        *(float2*)&o1[n*8 + 2*t] = make_float2(Oa[n][2]*inv1, Oa[n][3]*inv1);
    }
}

extern "C" void kernel_launch(void* const* d_in, const int* in_sizes, int n_in,
                              void* d_out, int out_size)
{
    const float* q    = (const float*)d_in[0];
    const float* k    = (const float*)d_in[1];
    const float* v    = (const float*)d_in[2];
    const float* abia = (const float*)d_in[3];
    const float* amask= (const float*)d_in[4];
    const float* Wq   = (const float*)d_in[5];
    const float* bq   = (const float*)d_in[6];
    const float* Wk   = (const float*)d_in[7];
    const float* bk   = (const float*)d_in[8];
    const float* Wv   = (const float*)d_in[9];
    const float* bv   = (const float*)d_in[10];
    const float* Wo   = (const float*)d_in[11];
    const float* bo   = (const float*)d_in[12];
    float* out = (float*)d_out;

    float *Qp, *Kp_, *Vp, *Cp;
    uint32_t *WH, *WL;
    cudaGetSymbolAddress((void**)&Qp, g_Q);
    cudaGetSymbolAddress((void**)&Kp_, g_K);
    cudaGetSymbolAddress((void**)&Vp, g_V);
    cudaGetSymbolAddress((void**)&Cp, g_C);
    cudaGetSymbolAddress((void**)&WH, g_Wh);
    cudaGetSymbolAddress((void**)&WL, g_Wl);

    split_w_kernel<<<dim3(2048, 4), 256>>>(Wq, Wk, Wv, Wo, WH, WL);

    dim3 gb(HIDDEN / 128, ROWS / 128);     // (8, 32)
    gemm_bf3_kernel<<<gb, 256>>>(q, WH,            WL,            bq, Qp);
    gemm_bf3_kernel<<<gb, 256>>>(k, WH + 524288u,  WL + 524288u,  bk, Kp_);
    gemm_bf3_kernel<<<gb, 256>>>(v, WH + 1048576u, WL + 1048576u, bv, Vp);

    dim3 gf(HEADS, NN / 128, BB);          // (16, 16, 2)
    flash_kernel<<<gf, 256>>>(abia, amask, Cp);

    gemm_bf3_kernel<<<gb, 256>>>(Cp, WH + 1572864u, WL + 1572864u, bo, out);
}

// round 13
// speedup vs baseline: 1.2669x; 1.0717x over previous
#include <cuda_runtime.h>
#include <cstdint>

#define HIDDEN 1024
#define HEADS  16
#define DKH    64
#define BB     2
#define NN     2048
#define ROWS   (BB*NN)

__device__ float g_Q[ROWS * HIDDEN];
__device__ float g_K[ROWS * HIDDEN];
__device__ float g_V[ROWS * HIDDEN];
__device__ float g_C[ROWS * HIDDEN];
__device__ float g_BM[(size_t)BB * NN * NN];      // bias + mask (33.5 MB)
// K-major bf16-split weights: [4 mats][512 kpairs][1024 n] u32 (h and l)
__device__ uint32_t g_Wh[4u * 512u * 1024u];
__device__ uint32_t g_Wl[4u * 512u * 1024u];

__device__ __forceinline__ uint32_t f2tf(float x) {
    uint32_t u; asm("cvt.rna.tf32.f32 %0, %1;" : "=r"(u) : "f"(x)); return u;
}
__device__ __forceinline__ uint32_t pk(float a, float b) {
    uint32_t r; asm("cvt.rn.bf16x2.f32 %0, %1, %2;" : "=r"(r) : "f"(b), "f"(a)); return r;
}
__device__ __forceinline__ float blo(uint32_t u) { return __uint_as_float(u << 16); }
__device__ __forceinline__ float bhi(uint32_t u) { return __uint_as_float(u & 0xffff0000u); }
__device__ __forceinline__ void sp(float f0, float f1, uint32_t& h, uint32_t& l) {
    h = pk(f0, f1);
    l = pk(f0 - blo(h), f1 - bhi(h));
}
__device__ __forceinline__ uint32_t smem_u32(const void* p) {
    uint32_t a;
    asm("{ .reg .u64 t; cvta.to.shared.u64 t, %1; cvt.u32.u64 %0, t; }" : "=r"(a) : "l"(p));
    return a;
}
__device__ __forceinline__ void cp16(uint32_t dst, const void* src) {
    asm volatile("cp.async.ca.shared.global [%0], [%1], 16;"
                 :: "r"(dst), "l"(src) : "memory");
}
__device__ __forceinline__ void mma8(float* d, uint32_t a0, uint32_t a1,
    uint32_t a2, uint32_t a3, uint32_t b0, uint32_t b1) {
    asm volatile("mma.sync.aligned.m16n8k8.row.col.f32.tf32.tf32.f32 "
        "{%0,%1,%2,%3},{%4,%5,%6,%7},{%8,%9},{%0,%1,%2,%3};"
        : "+f"(d[0]), "+f"(d[1]), "+f"(d[2]), "+f"(d[3])
        : "r"(a0), "r"(a1), "r"(a2), "r"(a3), "r"(b0), "r"(b1));
}
__device__ __forceinline__ void mma16(float* d, uint32_t a0, uint32_t a1,
    uint32_t a2, uint32_t a3, uint32_t b0, uint32_t b1) {
    asm volatile("mma.sync.aligned.m16n8k16.row.col.f32.bf16.bf16.f32 "
        "{%0,%1,%2,%3},{%4,%5,%6,%7},{%8,%9},{%0,%1,%2,%3};"
        : "+f"(d[0]), "+f"(d[1]), "+f"(d[2]), "+f"(d[3])
        : "r"(a0), "r"(a1), "r"(a2), "r"(a3), "r"(b0), "r"(b1));
}

// ---------------------------------------------------------------------------
// bm = bias + mask (33.5 MB, one pass)
// ---------------------------------------------------------------------------
__global__ void add_bm_kernel(const float* __restrict__ a,
                              const float* __restrict__ m,
                              float* __restrict__ o)
{
    int i = blockIdx.x * 256 + threadIdx.x;
    float4 x = ((const float4*)a)[i];
    float4 y = ((const float4*)m)[i];
    x.x += y.x; x.y += y.y; x.z += y.z; x.w += y.w;
    ((float4*)o)[i] = x;
}

// ---------------------------------------------------------------------------
// One-shot: split W (K-major) into bf16 (h,l) pair arrays.
// ---------------------------------------------------------------------------
__global__ void split_w_kernel(
    const float* __restrict__ W0, const float* __restrict__ W1,
    const float* __restrict__ W2, const float* __restrict__ W3,
    uint32_t* __restrict__ outH, uint32_t* __restrict__ outL)
{
    const float* W = (blockIdx.y == 0) ? W0 : (blockIdx.y == 1) ? W1
                   : (blockIdx.y == 2) ? W2 : W3;
    uint32_t* oh = outH + (size_t)blockIdx.y * 524288u;
    uint32_t* ol = outL + (size_t)blockIdx.y * 524288u;
    int idx = blockIdx.x * 256 + threadIdx.x;
    int kp = idx >> 10, n = idx & 1023;
    float w0 = W[(size_t)(2 * kp) * 1024 + n];
    float w1 = W[(size_t)(2 * kp + 1) * 1024 + n];
    uint32_t h, l;
    sp(w0, w1, h, l);
    oh[idx] = h; ol[idx] = l;
}

// ---------------------------------------------------------------------------
// bf16x3 GEMM — round-12 structure; W staged via cp.async (raw copies).
// BM=BN=128, BK=16, double-buffered, 2 CTA/SM.
// ---------------------------------------------------------------------------
__global__ void __launch_bounds__(256, 2) gemm_bf3_kernel(
    const float* __restrict__ A,
    const uint32_t* __restrict__ WhG, const uint32_t* __restrict__ WlG,
    const float* __restrict__ bias, float* __restrict__ C)
{
    __shared__ uint32_t Ah[2][8][136], Al[2][8][136], Wh[2][8][136], Wl[2][8][136];
    const int tid = threadIdx.x, lane = tid & 31, wid = tid >> 5;
    const int g = lane >> 2, t = lane & 3;
    const int wm = (wid & 3) * 32, wn = (wid >> 2) * 64;
    const float* Ab = A + (size_t)blockIdx.y * 128 * 1024;
    const uint32_t* WhB = WhG + blockIdx.x * 128;   // [kpair][1024 n]
    const uint32_t* WlB = WlG + blockIdx.x * 128;

    float acc[2][8][4];
#pragma unroll
    for (int mi = 0; mi < 2; mi++)
#pragma unroll
        for (int n = 0; n < 8; n++)
#pragma unroll
            for (int j = 0; j < 4; j++) acc[mi][n][j] = 0.f;

    const int arow = tid >> 2, ac4 = tid & 3;   // A rows arow, arow+64
    const int kp = tid >> 5, c4 = tid & 31;     // W kpair kp, cols c4*4..+3

    float4 ra0, ra1;
#define A_LOAD(k0) do { \
    ra0 = *(const float4*)(Ab + (size_t)arow * 1024 + (k0) + ac4 * 4); \
    ra1 = *(const float4*)(Ab + (size_t)(arow + 64) * 1024 + (k0) + ac4 * 4); \
} while (0)
#define W_CP(pb, k0) do { \
    cp16(smem_u32(&Wh[pb][kp][c4 * 4]), WhB + (size_t)(((k0) >> 1) + kp) * 1024 + c4 * 4); \
    cp16(smem_u32(&Wl[pb][kp][c4 * 4]), WlB + (size_t)(((k0) >> 1) + kp) * 1024 + c4 * 4); \
    asm volatile("cp.async.commit_group;" ::: "memory"); \
} while (0)
#define A_STS(pb) do { \
    uint32_t h_, l_; \
    sp(ra0.x, ra0.y, h_, l_); Ah[pb][2*ac4][arow] = h_;      Al[pb][2*ac4][arow] = l_; \
    sp(ra0.z, ra0.w, h_, l_); Ah[pb][2*ac4+1][arow] = h_;    Al[pb][2*ac4+1][arow] = l_; \
    sp(ra1.x, ra1.y, h_, l_); Ah[pb][2*ac4][arow+64] = h_;   Al[pb][2*ac4][arow+64] = l_; \
    sp(ra1.z, ra1.w, h_, l_); Ah[pb][2*ac4+1][arow+64] = h_; Al[pb][2*ac4+1][arow+64] = l_; \
} while (0)

    A_LOAD(0);
    W_CP(0, 0);
    A_STS(0);
    asm volatile("cp.async.wait_group 0;" ::: "memory");
    __syncthreads();
    int p = 0;

    for (int k0 = 0; k0 < 1024; k0 += 16) {
        if (k0 + 16 < 1024) {
            A_LOAD(k0 + 16);
            W_CP(p ^ 1, k0 + 16);
        }

        uint32_t af[2][8];
#pragma unroll
        for (int mi = 0; mi < 2; mi++) {
            int mb = wm + mi * 16;
            af[mi][0] = Ah[p][t][mb+g];   af[mi][1] = Ah[p][t][mb+g+8];
            af[mi][2] = Ah[p][t+4][mb+g]; af[mi][3] = Ah[p][t+4][mb+g+8];
            af[mi][4] = Al[p][t][mb+g];   af[mi][5] = Al[p][t][mb+g+8];
            af[mi][6] = Al[p][t+4][mb+g]; af[mi][7] = Al[p][t+4][mb+g+8];
        }
#pragma unroll
        for (int n = 0; n < 8; n++) {
            uint32_t b0h = Wh[p][t][wn+n*8+g], b1h = Wh[p][t+4][wn+n*8+g];
            uint32_t b0l = Wl[p][t][wn+n*8+g], b1l = Wl[p][t+4][wn+n*8+g];
#pragma unroll
            for (int mi = 0; mi < 2; mi++) {
                mma16(acc[mi][n], af[mi][0], af[mi][1], af[mi][2], af[mi][3], b0h, b1h);
                mma16(acc[mi][n], af[mi][4], af[mi][5], af[mi][6], af[mi][7], b0h, b1h);
                mma16(acc[mi][n], af[mi][0], af[mi][1], af[mi][2], af[mi][3], b0l, b1l);
            }
        }
        if (k0 + 16 < 1024) {
            A_STS(p ^ 1);
            asm volatile("cp.async.wait_group 0;" ::: "memory");
        }
        __syncthreads();
        p ^= 1;
    }

#pragma unroll
    for (int mi = 0; mi < 2; mi++) {
        int row0 = blockIdx.y * 128 + wm + mi * 16 + g;
#pragma unroll
        for (int n = 0; n < 8; n++) {
            int col = blockIdx.x * 128 + wn + n * 8 + 2 * t;
            float2 bv = *(const float2*)(bias + col);
            *(float2*)(C + (size_t)row0 * 1024 + col) =
                make_float2(acc[mi][n][0] + bv.x, acc[mi][n][1] + bv.y);
            *(float2*)(C + (size_t)(row0 + 8) * 1024 + col) =
                make_float2(acc[mi][n][2] + bv.x, acc[mi][n][3] + bv.y);
        }
    }
}

// ---------------------------------------------------------------------------
// Flash (round-9 structure; single pre-summed bm stream, 16 LDG.64/thread/tile
// instead of 32). Br=128, Bc=64, launch_bounds(256,2).
// ---------------------------------------------------------------------------
__global__ void __launch_bounds__(256, 2) flash_kernel(
    const float* __restrict__ bm, float* __restrict__ ctx)
{
    __shared__ uint32_t Kp[64 * 72];
    __shared__ uint32_t Vhl[32 * 136];

    const int tid = threadIdx.x, lane = tid & 31, wid = tid >> 5;
    const int g = lane >> 2, t = lane & 3;
    const int wrow = wid * 16;
    const int h = blockIdx.x, q0 = blockIdx.y * 128, b = blockIdx.z;

    const float* Qg = g_Q + ((size_t)b * NN + q0) * HIDDEN + h * DKH;
    const float* Kg = g_K + (size_t)b * NN * HIDDEN + h * DKH;
    const float* Vg = g_V + (size_t)b * NN * HIDDEN + h * DKH;

    const float L2E = 1.44269504088896340736f;
    const float QSC = 0.125f * L2E;

    uint32_t qa[8][4];
#pragma unroll
    for (int kb = 0; kb < 8; kb++) {
        qa[kb][0] = f2tf(__ldg(Qg + (size_t)(wrow+g)  *HIDDEN + kb*8 + t)   * QSC);
        qa[kb][1] = f2tf(__ldg(Qg + (size_t)(wrow+g+8)*HIDDEN + kb*8 + t)   * QSC);
        qa[kb][2] = f2tf(__ldg(Qg + (size_t)(wrow+g)  *HIDDEN + kb*8 + t+4) * QSC);
        qa[kb][3] = f2tf(__ldg(Qg + (size_t)(wrow+g+8)*HIDDEN + kb*8 + t+4) * QSC);
    }

    float Oa[8][4];
#pragma unroll
    for (int n = 0; n < 8; n++)
#pragma unroll
        for (int j = 0; j < 4; j++) Oa[n][j] = 0.f;
    float m0 = -1e30f, m1 = -1e30f, l0 = 0.f, l1 = 0.f;

    const float* bmB = bm + ((size_t)b * NN + q0 + wrow) * NN;

    const int kkey = tid >> 3, kkb = tid & 7;
    const int vrp  = tid >> 4, vdq = tid & 15;

    for (int kt = 0; kt < NN / 64; kt++) {
        const int k0 = kt * 64;
        __syncthreads();

#pragma unroll
        for (int i = 0; i < 2; i++) {
            int key = kkey + i * 32;
            const float* kr = Kg + (size_t)(k0 + key) * HIDDEN + kkb * 8;
            float4 fa = *(const float4*)kr;
            float4 fb = *(const float4*)(kr + 4);
            uint32_t* d = &Kp[key * 72 + kkb * 8];
            *(uint4*)d       = make_uint4(f2tf(fa.x), f2tf(fb.x), f2tf(fa.y), f2tf(fb.y));
            *(uint4*)(d + 4) = make_uint4(f2tf(fa.z), f2tf(fb.z), f2tf(fa.w), f2tf(fb.w));
        }
#pragma unroll
        for (int i = 0; i < 2; i++) {
            int rp = vrp + i * 16;
            const float* vr = Vg + (size_t)(k0 + 2 * rp) * HIDDEN + vdq * 4;
            float4 f0 = *(const float4*)vr;
            float4 f1 = *(const float4*)(vr + HIDDEN);
            uint4 u0, u1;
            sp(f0.x, f1.x, u0.x, u0.y); sp(f0.y, f1.y, u0.z, u0.w);
            sp(f0.z, f1.z, u1.x, u1.y); sp(f0.w, f1.w, u1.z, u1.w);
            uint32_t* d = &Vhl[rp * 136 + vdq * 8];
            *(uint4*)d       = u0;
            *(uint4*)(d + 4) = u1;
        }
        __syncthreads();

        float sacc[8][4];
#pragma unroll
        for (int n = 0; n < 8; n++)
#pragma unroll
            for (int j = 0; j < 4; j++) sacc[n][j] = 0.f;
#pragma unroll
        for (int kb = 0; kb < 8; kb++)
#pragma unroll
            for (int n = 0; n < 8; n++) {
                uint2 bb = *(const uint2*)&Kp[(n*8+g) * 72 + kb*8 + 2*t];
                mma8(sacc[n], qa[kb][0], qa[kb][1], qa[kb][2], qa[kb][3], bb.x, bb.y);
            }

        float mx0 = -1e30f, mx1 = -1e30f;
#pragma unroll
        for (int n = 0; n < 8; n++) {
            float2 u = __ldg((const float2*)(bmB + (size_t)g    * NN + k0 + n*8 + 2*t));
            float2 w = __ldg((const float2*)(bmB + (size_t)(g+8)* NN + k0 + n*8 + 2*t));
            sacc[n][0] = fmaf(u.x, L2E, sacc[n][0]);
            sacc[n][1] = fmaf(u.y, L2E, sacc[n][1]);
            sacc[n][2] = fmaf(w.x, L2E, sacc[n][2]);
            sacc[n][3] = fmaf(w.y, L2E, sacc[n][3]);
            mx0 = fmaxf(mx0, fmaxf(sacc[n][0], sacc[n][1]));
            mx1 = fmaxf(mx1, fmaxf(sacc[n][2], sacc[n][3]));
        }
        mx0 = fmaxf(mx0, __shfl_xor_sync(~0u, mx0, 1));
        mx0 = fmaxf(mx0, __shfl_xor_sync(~0u, mx0, 2));
        mx1 = fmaxf(mx1, __shfl_xor_sync(~0u, mx1, 1));
        mx1 = fmaxf(mx1, __shfl_xor_sync(~0u, mx1, 2));
        float mn0 = fmaxf(m0, mx0), mn1 = fmaxf(m1, mx1);
        float c0 = exp2f(m0 - mn0), c1 = exp2f(m1 - mn1);
        float rs0 = 0.f, rs1 = 0.f;
#pragma unroll
        for (int n = 0; n < 8; n++) {
            sacc[n][0] = exp2f(sacc[n][0] - mn0);
            sacc[n][1] = exp2f(sacc[n][1] - mn0);
            sacc[n][2] = exp2f(sacc[n][2] - mn1);
            sacc[n][3] = exp2f(sacc[n][3] - mn1);
            rs0 += sacc[n][0] + sacc[n][1];
            rs1 += sacc[n][2] + sacc[n][3];
        }
        rs0 += __shfl_xor_sync(~0u, rs0, 1); rs0 += __shfl_xor_sync(~0u, rs0, 2);
        rs1 += __shfl_xor_sync(~0u, rs1, 1); rs1 += __shfl_xor_sync(~0u, rs1, 2);
        l0 = l0 * c0 + rs0; l1 = l1 * c1 + rs1;
        m0 = mn0; m1 = mn1;
#pragma unroll
        for (int n = 0; n < 8; n++) {
            Oa[n][0] *= c0; Oa[n][1] *= c0;
            Oa[n][2] *= c1; Oa[n][3] *= c1;
        }

#pragma unroll
        for (int kb = 0; kb < 4; kb++) {
            uint32_t a0h, a0l, a1h, a1l, a2h, a2l, a3h, a3l;
            sp(sacc[2*kb][0],   sacc[2*kb][1],   a0h, a0l);
            sp(sacc[2*kb][2],   sacc[2*kb][3],   a1h, a1l);
            sp(sacc[2*kb+1][0], sacc[2*kb+1][1], a2h, a2l);
            sp(sacc[2*kb+1][2], sacc[2*kb+1][3], a3h, a3l);
#pragma unroll
            for (int n = 0; n < 8; n++) {
                uint2 p0 = *(const uint2*)&Vhl[(kb*8+t)   * 136 + (n*8+g) * 2];
                uint2 p1 = *(const uint2*)&Vhl[(kb*8+t+4) * 136 + (n*8+g) * 2];
                mma16(Oa[n], a0h, a1h, a2h, a3h, p0.x, p1.x);
                mma16(Oa[n], a0l, a1l, a2l, a3l, p0.x, p1.x);
                mma16(Oa[n], a0h, a1h, a2h, a3h, p0.y, p1.y);
            }
        }
    }

    float inv0 = 1.f / l0, inv1 = 1.f / l1;
    float* o0 = ctx + ((size_t)b * NN + q0 + wrow + g) * HIDDEN + h * DKH;
    float* o1 = o0 + (size_t)8 * HIDDEN;
#pragma unroll
    for (int n = 0; n < 8; n++) {
        *(float2*)&o0[n*8 + 2*t] = make_float2(Oa[n][0]*inv0, Oa[n][1]*inv0);
        *(float2*)&o1[n*8 + 2*t] = make_float2(Oa[n][2]*inv1, Oa[n][3]*inv1);
    }
}

extern "C" void kernel_launch(void* const* d_in, const int* in_sizes, int n_in,
                              void* d_out, int out_size)
{
    const float* q    = (const float*)d_in[0];
    const float* k    = (const float*)d_in[1];
    const float* v    = (const float*)d_in[2];
    const float* abia = (const float*)d_in[3];
    const float* amask= (const float*)d_in[4];
    const float* Wq   = (const float*)d_in[5];
    const float* bq   = (const float*)d_in[6];
    const float* Wk   = (const float*)d_in[7];
    const float* bk   = (const float*)d_in[8];
    const float* Wv   = (const float*)d_in[9];
    const float* bv   = (const float*)d_in[10];
    const float* Wo   = (const float*)d_in[11];
    const float* bo   = (const float*)d_in[12];
    float* out = (float*)d_out;

    float *Qp, *Kp_, *Vp, *Cp, *BMp;
    uint32_t *WH, *WL;
    cudaGetSymbolAddress((void**)&Qp, g_Q);
    cudaGetSymbolAddress((void**)&Kp_, g_K);
    cudaGetSymbolAddress((void**)&Vp, g_V);
    cudaGetSymbolAddress((void**)&Cp, g_C);
    cudaGetSymbolAddress((void**)&BMp, g_BM);
    cudaGetSymbolAddress((void**)&WH, g_Wh);
    cudaGetSymbolAddress((void**)&WL, g_Wl);

    split_w_kernel<<<dim3(2048, 4), 256>>>(Wq, Wk, Wv, Wo, WH, WL);
    add_bm_kernel<<<8192, 256>>>(abia, amask, BMp);

    dim3 gb(HIDDEN / 128, ROWS / 128);     // (8, 32)
    gemm_bf3_kernel<<<gb, 256>>>(q, WH,            WL,            bq, Qp);
    gemm_bf3_kernel<<<gb, 256>>>(k, WH + 524288u,  WL + 524288u,  bk, Kp_);
    gemm_bf3_kernel<<<gb, 256>>>(v, WH + 1048576u, WL + 1048576u, bv, Vp);

    dim3 gf(HEADS, NN / 128, BB);          // (16, 16, 2)
    flash_kernel<<<gf, 256>>>(BMp, Cp);

    gemm_bf3_kernel<<<gb, 256>>>(Cp, WH + 1572864u, WL + 1572864u, bo, out);
}

// round 14
// speedup vs baseline: 1.3243x; 1.0453x over previous
#include <cuda_runtime.h>
#include <cstdint>

#define HIDDEN 1024
#define HEADS  16
#define DKH    64
#define BB     2
#define NN     2048
#define ROWS   (BB*NN)

__device__ float g_Q[ROWS * HIDDEN];
__device__ float g_K[ROWS * HIDDEN];
__device__ float g_V[ROWS * HIDDEN];
__device__ float g_C[ROWS * HIDDEN];
__device__ float g_BM[(size_t)BB * NN * NN];      // bias + mask (33.5 MB)
// K-major bf16-split weights: [4 mats][512 kpairs][1024 n] u32 (h and l)
__device__ uint32_t g_Wh[4u * 512u * 1024u];
__device__ uint32_t g_Wl[4u * 512u * 1024u];

__device__ __forceinline__ uint32_t f2tf(float x) {
    uint32_t u; asm("cvt.rna.tf32.f32 %0, %1;" : "=r"(u) : "f"(x)); return u;
}
__device__ __forceinline__ uint32_t pk(float a, float b) {
    uint32_t r; asm("cvt.rn.bf16x2.f32 %0, %1, %2;" : "=r"(r) : "f"(b), "f"(a)); return r;
}
__device__ __forceinline__ float blo(uint32_t u) { return __uint_as_float(u << 16); }
__device__ __forceinline__ float bhi(uint32_t u) { return __uint_as_float(u & 0xffff0000u); }
__device__ __forceinline__ void sp(float f0, float f1, uint32_t& h, uint32_t& l) {
    h = pk(f0, f1);
    l = pk(f0 - blo(h), f1 - bhi(h));
}
__device__ __forceinline__ void mma8(float* d, uint32_t a0, uint32_t a1,
    uint32_t a2, uint32_t a3, uint32_t b0, uint32_t b1) {
    asm volatile("mma.sync.aligned.m16n8k8.row.col.f32.tf32.tf32.f32 "
        "{%0,%1,%2,%3},{%4,%5,%6,%7},{%8,%9},{%0,%1,%2,%3};"
        : "+f"(d[0]), "+f"(d[1]), "+f"(d[2]), "+f"(d[3])
        : "r"(a0), "r"(a1), "r"(a2), "r"(a3), "r"(b0), "r"(b1));
}
__device__ __forceinline__ void mma16(float* d, uint32_t a0, uint32_t a1,
    uint32_t a2, uint32_t a3, uint32_t b0, uint32_t b1) {
    asm volatile("mma.sync.aligned.m16n8k16.row.col.f32.bf16.bf16.f32 "
        "{%0,%1,%2,%3},{%4,%5,%6,%7},{%8,%9},{%0,%1,%2,%3};"
        : "+f"(d[0]), "+f"(d[1]), "+f"(d[2]), "+f"(d[3])
        : "r"(a0), "r"(a1), "r"(a2), "r"(a3), "r"(b0), "r"(b1));
}

// ---------------------------------------------------------------------------
// bm = bias + mask (33.5 MB, one pass)
// ---------------------------------------------------------------------------
__global__ void add_bm_kernel(const float* __restrict__ a,
                              const float* __restrict__ m,
                              float* __restrict__ o)
{
    int i = blockIdx.x * 256 + threadIdx.x;
    float4 x = ((const float4*)a)[i];
    float4 y = ((const float4*)m)[i];
    x.x += y.x; x.y += y.y; x.z += y.z; x.w += y.w;
    ((float4*)o)[i] = x;
}

// ---------------------------------------------------------------------------
// One-shot: split W (K-major) into bf16 (h,l) pair arrays.
// ---------------------------------------------------------------------------
__global__ void split_w_kernel(
    const float* __restrict__ W0, const float* __restrict__ W1,
    const float* __restrict__ W2, const float* __restrict__ W3,
    uint32_t* __restrict__ outH, uint32_t* __restrict__ outL)
{
    const float* W = (blockIdx.y == 0) ? W0 : (blockIdx.y == 1) ? W1
                   : (blockIdx.y == 2) ? W2 : W3;
    uint32_t* oh = outH + (size_t)blockIdx.y * 524288u;
    uint32_t* ol = outL + (size_t)blockIdx.y * 524288u;
    int idx = blockIdx.x * 256 + threadIdx.x;
    int kp = idx >> 10, n = idx & 1023;
    float w0 = W[(size_t)(2 * kp) * 1024 + n];
    float w1 = W[(size_t)(2 * kp + 1) * 1024 + n];
    uint32_t h, l;
    sp(w0, w1, h, l);
    oh[idx] = h; ol[idx] = l;
}

// ---------------------------------------------------------------------------
// bf16x3 GEMM — round-12 mainloop exactly (LDG+reg double-buffer; measured
// 81.6us). Batched: blockIdx.z selects one of up to 3 (A, bias, C) triples
// sharing the W slab base (W slice = z * 524288).
// ---------------------------------------------------------------------------
__global__ void __launch_bounds__(256, 2) gemm_bf3_kernel(
    const float* __restrict__ A0, const float* __restrict__ A1,
    const float* __restrict__ A2,
    const uint32_t* __restrict__ WhG, const uint32_t* __restrict__ WlG,
    const float* __restrict__ b0, const float* __restrict__ b1,
    const float* __restrict__ b2,
    float* __restrict__ C0, float* __restrict__ C1, float* __restrict__ C2)
{
    __shared__ uint32_t Ah[2][8][136], Al[2][8][136], Wh[2][8][136], Wl[2][8][136];
    const int tid = threadIdx.x, lane = tid & 31, wid = tid >> 5;
    const int g = lane >> 2, t = lane & 3;
    const int wm = (wid & 3) * 32, wn = (wid >> 2) * 64;
    const int z = blockIdx.z;

    const float* A    = (z == 0) ? A0 : (z == 1) ? A1 : A2;
    const float* bias = (z == 0) ? b0 : (z == 1) ? b1 : b2;
    float*       C    = (z == 0) ? C0 : (z == 1) ? C1 : C2;

    const float* Ab = A + (size_t)blockIdx.y * 128 * 1024;
    const uint32_t* WhB = WhG + (size_t)z * 524288u + blockIdx.x * 128;
    const uint32_t* WlB = WlG + (size_t)z * 524288u + blockIdx.x * 128;

    float acc[2][8][4];
#pragma unroll
    for (int mi = 0; mi < 2; mi++)
#pragma unroll
        for (int n = 0; n < 8; n++)
#pragma unroll
            for (int j = 0; j < 4; j++) acc[mi][n][j] = 0.f;

    const int arow = tid >> 2, ac4 = tid & 3;   // A rows arow, arow+64
    const int kp = tid >> 5, c4 = tid & 31;     // W kpair kp, cols c4*4..+3

    float4 ra0, ra1;
    uint4 rwh, rwl;
#define G_LOAD(k0) do { \
    ra0 = *(const float4*)(Ab + (size_t)arow * 1024 + (k0) + ac4 * 4); \
    ra1 = *(const float4*)(Ab + (size_t)(arow + 64) * 1024 + (k0) + ac4 * 4); \
    rwh = *(const uint4*)(WhB + (size_t)(((k0) >> 1) + kp) * 1024 + c4 * 4); \
    rwl = *(const uint4*)(WlB + (size_t)(((k0) >> 1) + kp) * 1024 + c4 * 4); \
} while (0)
#define G_STS(pb) do { \
    uint32_t h_, l_; \
    sp(ra0.x, ra0.y, h_, l_); Ah[pb][2*ac4][arow] = h_;      Al[pb][2*ac4][arow] = l_; \
    sp(ra0.z, ra0.w, h_, l_); Ah[pb][2*ac4+1][arow] = h_;    Al[pb][2*ac4+1][arow] = l_; \
    sp(ra1.x, ra1.y, h_, l_); Ah[pb][2*ac4][arow+64] = h_;   Al[pb][2*ac4][arow+64] = l_; \
    sp(ra1.z, ra1.w, h_, l_); Ah[pb][2*ac4+1][arow+64] = h_; Al[pb][2*ac4+1][arow+64] = l_; \
    *(uint4*)&Wh[pb][kp][c4 * 4] = rwh; \
    *(uint4*)&Wl[pb][kp][c4 * 4] = rwl; \
} while (0)

    G_LOAD(0);
    G_STS(0);
    __syncthreads();
    int p = 0;

    for (int k0 = 0; k0 < 1024; k0 += 16) {
        if (k0 + 16 < 1024) G_LOAD(k0 + 16);

        uint32_t af[2][8];
#pragma unroll
        for (int mi = 0; mi < 2; mi++) {
            int mb = wm + mi * 16;
            af[mi][0] = Ah[p][t][mb+g];   af[mi][1] = Ah[p][t][mb+g+8];
            af[mi][2] = Ah[p][t+4][mb+g]; af[mi][3] = Ah[p][t+4][mb+g+8];
            af[mi][4] = Al[p][t][mb+g];   af[mi][5] = Al[p][t][mb+g+8];
            af[mi][6] = Al[p][t+4][mb+g]; af[mi][7] = Al[p][t+4][mb+g+8];
        }
#pragma unroll
        for (int n = 0; n < 8; n++) {
            uint32_t b0h = Wh[p][t][wn+n*8+g], b1h = Wh[p][t+4][wn+n*8+g];
            uint32_t b0l = Wl[p][t][wn+n*8+g], b1l = Wl[p][t+4][wn+n*8+g];
#pragma unroll
            for (int mi = 0; mi < 2; mi++) {
                mma16(acc[mi][n], af[mi][0], af[mi][1], af[mi][2], af[mi][3], b0h, b1h);
                mma16(acc[mi][n], af[mi][4], af[mi][5], af[mi][6], af[mi][7], b0h, b1h);
                mma16(acc[mi][n], af[mi][0], af[mi][1], af[mi][2], af[mi][3], b0l, b1l);
            }
        }
        if (k0 + 16 < 1024) G_STS(p ^ 1);
        __syncthreads();
        p ^= 1;
    }

#pragma unroll
    for (int mi = 0; mi < 2; mi++) {
        int row0 = blockIdx.y * 128 + wm + mi * 16 + g;
#pragma unroll
        for (int n = 0; n < 8; n++) {
            int col = blockIdx.x * 128 + wn + n * 8 + 2 * t;
            float2 bv = *(const float2*)(bias + col);
            *(float2*)(C + (size_t)row0 * 1024 + col) =
                make_float2(acc[mi][n][0] + bv.x, acc[mi][n][1] + bv.y);
            *(float2*)(C + (size_t)(row0 + 8) * 1024 + col) =
                make_float2(acc[mi][n][2] + bv.x, acc[mi][n][3] + bv.y);
        }
    }
}

// ---------------------------------------------------------------------------
// Flash (round-13 verbatim): pre-summed bm stream, Br=128, Bc=64,
// launch_bounds(256,2).
// ---------------------------------------------------------------------------
__global__ void __launch_bounds__(256, 2) flash_kernel(
    const float* __restrict__ bm, float* __restrict__ ctx)
{
    __shared__ uint32_t Kp[64 * 72];
    __shared__ uint32_t Vhl[32 * 136];

    const int tid = threadIdx.x, lane = tid & 31, wid = tid >> 5;
    const int g = lane >> 2, t = lane & 3;
    const int wrow = wid * 16;
    const int h = blockIdx.x, q0 = blockIdx.y * 128, b = blockIdx.z;

    const float* Qg = g_Q + ((size_t)b * NN + q0) * HIDDEN + h * DKH;
    const float* Kg = g_K + (size_t)b * NN * HIDDEN + h * DKH;
    const float* Vg = g_V + (size_t)b * NN * HIDDEN + h * DKH;

    const float L2E = 1.44269504088896340736f;
    const float QSC = 0.125f * L2E;

    uint32_t qa[8][4];
#pragma unroll
    for (int kb = 0; kb < 8; kb++) {
        qa[kb][0] = f2tf(__ldg(Qg + (size_t)(wrow+g)  *HIDDEN + kb*8 + t)   * QSC);
        qa[kb][1] = f2tf(__ldg(Qg + (size_t)(wrow+g+8)*HIDDEN + kb*8 + t)   * QSC);
        qa[kb][2] = f2tf(__ldg(Qg + (size_t)(wrow+g)  *HIDDEN + kb*8 + t+4) * QSC);
        qa[kb][3] = f2tf(__ldg(Qg + (size_t)(wrow+g+8)*HIDDEN + kb*8 + t+4) * QSC);
    }

    float Oa[8][4];
#pragma unroll
    for (int n = 0; n < 8; n++)
#pragma unroll
        for (int j = 0; j < 4; j++) Oa[n][j] = 0.f;
    float m0 = -1e30f, m1 = -1e30f, l0 = 0.f, l1 = 0.f;

    const float* bmB = bm + ((size_t)b * NN + q0 + wrow) * NN;

    const int kkey = tid >> 3, kkb = tid & 7;
    const int vrp  = tid >> 4, vdq = tid & 15;

    for (int kt = 0; kt < NN / 64; kt++) {
        const int k0 = kt * 64;
        __syncthreads();

#pragma unroll
        for (int i = 0; i < 2; i++) {
            int key = kkey + i * 32;
            const float* kr = Kg + (size_t)(k0 + key) * HIDDEN + kkb * 8;
            float4 fa = *(const float4*)kr;
            float4 fb = *(const float4*)(kr + 4);
            uint32_t* d = &Kp[key * 72 + kkb * 8];
            *(uint4*)d       = make_uint4(f2tf(fa.x), f2tf(fb.x), f2tf(fa.y), f2tf(fb.y));
            *(uint4*)(d + 4) = make_uint4(f2tf(fa.z), f2tf(fb.z), f2tf(fa.w), f2tf(fb.w));
        }
#pragma unroll
        for (int i = 0; i < 2; i++) {
            int rp = vrp + i * 16;
            const float* vr = Vg + (size_t)(k0 + 2 * rp) * HIDDEN + vdq * 4;
            float4 f0 = *(const float4*)vr;
            float4 f1 = *(const float4*)(vr + HIDDEN);
            uint4 u0, u1;
            sp(f0.x, f1.x, u0.x, u0.y); sp(f0.y, f1.y, u0.z, u0.w);
            sp(f0.z, f1.z, u1.x, u1.y); sp(f0.w, f1.w, u1.z, u1.w);
            uint32_t* d = &Vhl[rp * 136 + vdq * 8];
            *(uint4*)d       = u0;
            *(uint4*)(d + 4) = u1;
        }
        __syncthreads();

        float sacc[8][4];
#pragma unroll
        for (int n = 0; n < 8; n++)
#pragma unroll
            for (int j = 0; j < 4; j++) sacc[n][j] = 0.f;
#pragma unroll
        for (int kb = 0; kb < 8; kb++)
#pragma unroll
            for (int n = 0; n < 8; n++) {
                uint2 bb = *(const uint2*)&Kp[(n*8+g) * 72 + kb*8 + 2*t];
                mma8(sacc[n], qa[kb][0], qa[kb][1], qa[kb][2], qa[kb][3], bb.x, bb.y);
            }

        float mx0 = -1e30f, mx1 = -1e30f;
#pragma unroll
        for (int n = 0; n < 8; n++) {
            float2 u = __ldg((const float2*)(bmB + (size_t)g    * NN + k0 + n*8 + 2*t));
            float2 w = __ldg((const float2*)(bmB + (size_t)(g+8)* NN + k0 + n*8 + 2*t));
            sacc[n][0] = fmaf(u.x, L2E, sacc[n][0]);
            sacc[n][1] = fmaf(u.y, L2E, sacc[n][1]);
            sacc[n][2] = fmaf(w.x, L2E, sacc[n][2]);
            sacc[n][3] = fmaf(w.y, L2E, sacc[n][3]);
            mx0 = fmaxf(mx0, fmaxf(sacc[n][0], sacc[n][1]));
            mx1 = fmaxf(mx1, fmaxf(sacc[n][2], sacc[n][3]));
        }
        mx0 = fmaxf(mx0, __shfl_xor_sync(~0u, mx0, 1));
        mx0 = fmaxf(mx0, __shfl_xor_sync(~0u, mx0, 2));
        mx1 = fmaxf(mx1, __shfl_xor_sync(~0u, mx1, 1));
        mx1 = fmaxf(mx1, __shfl_xor_sync(~0u, mx1, 2));
        float mn0 = fmaxf(m0, mx0), mn1 = fmaxf(m1, mx1);
        float c0 = exp2f(m0 - mn0), c1 = exp2f(m1 - mn1);
        float rs0 = 0.f, rs1 = 0.f;
#pragma unroll
        for (int n = 0; n < 8; n++) {
            sacc[n][0] = exp2f(sacc[n][0] - mn0);
            sacc[n][1] = exp2f(sacc[n][1] - mn0);
            sacc[n][2] = exp2f(sacc[n][2] - mn1);
            sacc[n][3] = exp2f(sacc[n][3] - mn1);
            rs0 += sacc[n][0] + sacc[n][1];
            rs1 += sacc[n][2] + sacc[n][3];
        }
        rs0 += __shfl_xor_sync(~0u, rs0, 1); rs0 += __shfl_xor_sync(~0u, rs0, 2);
        rs1 += __shfl_xor_sync(~0u, rs1, 1); rs1 += __shfl_xor_sync(~0u, rs1, 2);
        l0 = l0 * c0 + rs0; l1 = l1 * c1 + rs1;
        m0 = mn0; m1 = mn1;
#pragma unroll
        for (int n = 0; n < 8; n++) {
            Oa[n][0] *= c0; Oa[n][1] *= c0;
            Oa[n][2] *= c1; Oa[n][3] *= c1;
        }

#pragma unroll
        for (int kb = 0; kb < 4; kb++) {
            uint32_t a0h, a0l, a1h, a1l, a2h, a2l, a3h, a3l;
            sp(sacc[2*kb][0],   sacc[2*kb][1],   a0h, a0l);
            sp(sacc[2*kb][2],   sacc[2*kb][3],   a1h, a1l);
            sp(sacc[2*kb+1][0], sacc[2*kb+1][1], a2h, a2l);
            sp(sacc[2*kb+1][2], sacc[2*kb+1][3], a3h, a3l);
#pragma unroll
            for (int n = 0; n < 8; n++) {
                uint2 p0 = *(const uint2*)&Vhl[(kb*8+t)   * 136 + (n*8+g) * 2];
                uint2 p1 = *(const uint2*)&Vhl[(kb*8+t+4) * 136 + (n*8+g) * 2];
                mma16(Oa[n], a0h, a1h, a2h, a3h, p0.x, p1.x);
                mma16(Oa[n], a0l, a1l, a2l, a3l, p0.x, p1.x);
                mma16(Oa[n], a0h, a1h, a2h, a3h, p0.y, p1.y);
            }
        }
    }

    float inv0 = 1.f / l0, inv1 = 1.f / l1;
    float* o0 = ctx + ((size_t)b * NN + q0 + wrow + g) * HIDDEN + h * DKH;
    float* o1 = o0 + (size_t)8 * HIDDEN;
#pragma unroll
    for (int n = 0; n < 8; n++) {
        *(float2*)&o0[n*8 + 2*t] = make_float2(Oa[n][0]*inv0, Oa[n][1]*inv0);
        *(float2*)&o1[n*8 + 2*t] = make_float2(Oa[n][2]*inv1, Oa[n][3]*inv1);
    }
}

extern "C" void kernel_launch(void* const* d_in, const int* in_sizes, int n_in,
                              void* d_out, int out_size)
{
    const float* q    = (const float*)d_in[0];
    const float* k    = (const float*)d_in[1];
    const float* v    = (const float*)d_in[2];
    const float* abia = (const float*)d_in[3];
    const float* amask= (const float*)d_in[4];
    const float* Wq   = (const float*)d_in[5];
    const float* bq   = (const float*)d_in[6];
    const float* Wk   = (const float*)d_in[7];
    const float* bk   = (const float*)d_in[8];
    const float* Wv   = (const float*)d_in[9];
    const float* bv   = (const float*)d_in[10];
    const float* Wo   = (const float*)d_in[11];
    const float* bo   = (const float*)d_in[12];
    float* out = (float*)d_out;

    float *Qp, *Kp_, *Vp, *Cp, *BMp;
    uint32_t *WH, *WL;
    cudaGetSymbolAddress((void**)&Qp, g_Q);
    cudaGetSymbolAddress((void**)&Kp_, g_K);
    cudaGetSymbolAddress((void**)&Vp, g_V);
    cudaGetSymbolAddress((void**)&Cp, g_C);
    cudaGetSymbolAddress((void**)&BMp, g_BM);
    cudaGetSymbolAddress((void**)&WH, g_Wh);
    cudaGetSymbolAddress((void**)&WL, g_Wl);

    split_w_kernel<<<dim3(2048, 4), 256>>>(Wq, Wk, Wv, Wo, WH, WL);
    add_bm_kernel<<<8192, 256>>>(abia, amask, BMp);

    // batched Q/K/V projections (z = 0,1,2 -> W slices 0,1,2)
    dim3 gb3(HIDDEN / 128, ROWS / 128, 3);   // (8, 32, 3)
    gemm_bf3_kernel<<<gb3, 256>>>(q, k, v, WH, WL, bq, bk, bv, Qp, Kp_, Vp);

    dim3 gf(HEADS, NN / 128, BB);            // (16, 16, 2)
    flash_kernel<<<gf, 256>>>(BMp, Cp);

    // O projection (z = 0 -> W slice 3 via offset base)
    dim3 gb1(HIDDEN / 128, ROWS / 128, 1);
    gemm_bf3_kernel<<<gb1, 256>>>(Cp, Cp, Cp,
                                  WH + 1572864u, WL + 1572864u,
                                  bo, bo, bo, out, out, out);
}

// round 15
// speedup vs baseline: 1.3330x; 1.0066x over previous
#include <cuda_runtime.h>
#include <cstdint>

#define HIDDEN 1024
#define HEADS  16
#define DKH    64
#define BB     2
#define NN     2048
#define ROWS   (BB*NN)

__device__ float g_Q[ROWS * HIDDEN];
__device__ float g_K[ROWS * HIDDEN];
__device__ float g_V[ROWS * HIDDEN];
__device__ float g_C[ROWS * HIDDEN];
__device__ float g_BM[(size_t)BB * NN * NN];      // bias + mask (33.5 MB)
// flash-ready K: [bh(32)][key(2048)][64 u32]  (tf32, permuted slot order)
__device__ uint32_t g_Kt[ROWS * HIDDEN];
// flash-ready V: [bh(32)][rp(1024)][128 u32]  (bf16 (h,l) interleaved pairs)
__device__ uint32_t g_V2[ROWS * HIDDEN];
// K-major bf16-split weights: [4 mats][512 kpairs][1024 n] u32 (h and l)
__device__ uint32_t g_Wh[4u * 512u * 1024u];
__device__ uint32_t g_Wl[4u * 512u * 1024u];

__device__ __forceinline__ uint32_t f2tf(float x) {
    uint32_t u; asm("cvt.rna.tf32.f32 %0, %1;" : "=r"(u) : "f"(x)); return u;
}
__device__ __forceinline__ uint32_t pk(float a, float b) {
    uint32_t r; asm("cvt.rn.bf16x2.f32 %0, %1, %2;" : "=r"(r) : "f"(b), "f"(a)); return r;
}
__device__ __forceinline__ float blo(uint32_t u) { return __uint_as_float(u << 16); }
__device__ __forceinline__ float bhi(uint32_t u) { return __uint_as_float(u & 0xffff0000u); }
__device__ __forceinline__ void sp(float f0, float f1, uint32_t& h, uint32_t& l) {
    h = pk(f0, f1);
    l = pk(f0 - blo(h), f1 - bhi(h));
}
__device__ __forceinline__ void mma8(float* d, uint32_t a0, uint32_t a1,
    uint32_t a2, uint32_t a3, uint32_t b0, uint32_t b1) {
    asm volatile("mma.sync.aligned.m16n8k8.row.col.f32.tf32.tf32.f32 "
        "{%0,%1,%2,%3},{%4,%5,%6,%7},{%8,%9},{%0,%1,%2,%3};"
        : "+f"(d[0]), "+f"(d[1]), "+f"(d[2]), "+f"(d[3])
        : "r"(a0), "r"(a1), "r"(a2), "r"(a3), "r"(b0), "r"(b1));
}
__device__ __forceinline__ void mma16(float* d, uint32_t a0, uint32_t a1,
    uint32_t a2, uint32_t a3, uint32_t b0, uint32_t b1) {
    asm volatile("mma.sync.aligned.m16n8k16.row.col.f32.bf16.bf16.f32 "
        "{%0,%1,%2,%3},{%4,%5,%6,%7},{%8,%9},{%0,%1,%2,%3};"
        : "+f"(d[0]), "+f"(d[1]), "+f"(d[2]), "+f"(d[3])
        : "r"(a0), "r"(a1), "r"(a2), "r"(a3), "r"(b0), "r"(b1));
}

// ---------------------------------------------------------------------------
// bm = bias + mask (33.5 MB, one pass)
// ---------------------------------------------------------------------------
__global__ void add_bm_kernel(const float* __restrict__ a,
                              const float* __restrict__ m,
                              float* __restrict__ o)
{
    int i = blockIdx.x * 256 + threadIdx.x;
    float4 x = ((const float4*)a)[i];
    float4 y = ((const float4*)m)[i];
    x.x += y.x; x.y += y.y; x.z += y.z; x.w += y.w;
    ((float4*)o)[i] = x;
}

// ---------------------------------------------------------------------------
// One-shot: split W (K-major) into bf16 (h,l) pair arrays.
// ---------------------------------------------------------------------------
__global__ void split_w_kernel(
    const float* __restrict__ W0, const float* __restrict__ W1,
    const float* __restrict__ W2, const float* __restrict__ W3,
    uint32_t* __restrict__ outH, uint32_t* __restrict__ outL)
{
    const float* W = (blockIdx.y == 0) ? W0 : (blockIdx.y == 1) ? W1
                   : (blockIdx.y == 2) ? W2 : W3;
    uint32_t* oh = outH + (size_t)blockIdx.y * 524288u;
    uint32_t* ol = outL + (size_t)blockIdx.y * 524288u;
    int idx = blockIdx.x * 256 + threadIdx.x;
    int kp = idx >> 10, n = idx & 1023;
    float w0 = W[(size_t)(2 * kp) * 1024 + n];
    float w1 = W[(size_t)(2 * kp + 1) * 1024 + n];
    uint32_t h, l;
    sp(w0, w1, h, l);
    oh[idx] = h; ol[idx] = l;
}

// ---------------------------------------------------------------------------
// conv_k: g_K fp32 -> g_Kt tf32 in flash slot order.
// Slot group kkb*8: {d0, d4, d1, d5, d2, d6, d3, d7} of dims kkb*8+0..7.
// grid (64, 32): i = 0..16383 per bh; key = i>>3, kkb = i&7.
// ---------------------------------------------------------------------------
__global__ void conv_k_kernel(uint32_t* __restrict__ out)
{
    const int bh = blockIdx.y;               // b*16 + h
    const int b = bh >> 4, h = bh & 15;
    int i = blockIdx.x * 256 + threadIdx.x;  // 0..16383
    int key = i >> 3, kkb = i & 7;
    const float* src = g_K + ((size_t)(b * NN + key)) * HIDDEN + h * DKH + kkb * 8;
    float4 fa = *(const float4*)src;
    float4 fb = *(const float4*)(src + 4);
    uint32_t* dst = out + ((size_t)bh * NN + key) * 64 + kkb * 8;
    *(uint4*)dst       = make_uint4(f2tf(fa.x), f2tf(fb.x), f2tf(fa.y), f2tf(fb.y));
    *(uint4*)(dst + 4) = make_uint4(f2tf(fa.z), f2tf(fb.z), f2tf(fa.w), f2tf(fb.w));
}

// ---------------------------------------------------------------------------
// conv_v: g_V fp32 -> g_V2 bf16 (h,l) interleaved row-pairs.
// Slots [rp][d*2 + {0,1}] = sp(V[2rp][d], V[2rp+1][d]).
// grid (64, 32): i per bh; rp = i>>4, dq = i&15 (dims dq*4..+3).
// ---------------------------------------------------------------------------
__global__ void conv_v_kernel(uint32_t* __restrict__ out)
{
    const int bh = blockIdx.y;
    const int b = bh >> 4, h = bh & 15;
    int i = blockIdx.x * 256 + threadIdx.x;  // 0..16383
    int rp = i >> 4, dq = i & 15;
    const float* v0 = g_V + ((size_t)(b * NN + 2 * rp)) * HIDDEN + h * DKH + dq * 4;
    const float* v1 = v0 + HIDDEN;
    float4 f0 = *(const float4*)v0;
    float4 f1 = *(const float4*)v1;
    uint4 u0, u1;
    sp(f0.x, f1.x, u0.x, u0.y); sp(f0.y, f1.y, u0.z, u0.w);
    sp(f0.z, f1.z, u1.x, u1.y); sp(f0.w, f1.w, u1.z, u1.w);
    uint32_t* dst = out + ((size_t)bh * (NN / 2) + rp) * 128 + dq * 8;
    *(uint4*)dst       = u0;
    *(uint4*)(dst + 4) = u1;
}

// ---------------------------------------------------------------------------
// bf16x3 GEMM — round-12 mainloop (LDG+reg double-buffer). Batched via z.
// ---------------------------------------------------------------------------
__global__ void __launch_bounds__(256, 2) gemm_bf3_kernel(
    const float* __restrict__ A0, const float* __restrict__ A1,
    const float* __restrict__ A2,
    const uint32_t* __restrict__ WhG, const uint32_t* __restrict__ WlG,
    const float* __restrict__ b0, const float* __restrict__ b1,
    const float* __restrict__ b2,
    float* __restrict__ C0, float* __restrict__ C1, float* __restrict__ C2)
{
    __shared__ uint32_t Ah[2][8][136], Al[2][8][136], Wh[2][8][136], Wl[2][8][136];
    const int tid = threadIdx.x, lane = tid & 31, wid = tid >> 5;
    const int g = lane >> 2, t = lane & 3;
    const int wm = (wid & 3) * 32, wn = (wid >> 2) * 64;
    const int z = blockIdx.z;

    const float* A    = (z == 0) ? A0 : (z == 1) ? A1 : A2;
    const float* bias = (z == 0) ? b0 : (z == 1) ? b1 : b2;
    float*       C    = (z == 0) ? C0 : (z == 1) ? C1 : C2;

    const float* Ab = A + (size_t)blockIdx.y * 128 * 1024;
    const uint32_t* WhB = WhG + (size_t)z * 524288u + blockIdx.x * 128;
    const uint32_t* WlB = WlG + (size_t)z * 524288u + blockIdx.x * 128;

    float acc[2][8][4];
#pragma unroll
    for (int mi = 0; mi < 2; mi++)
#pragma unroll
        for (int n = 0; n < 8; n++)
#pragma unroll
            for (int j = 0; j < 4; j++) acc[mi][n][j] = 0.f;

    const int arow = tid >> 2, ac4 = tid & 3;
    const int kp = tid >> 5, c4 = tid & 31;

    float4 ra0, ra1;
    uint4 rwh, rwl;
#define G_LOAD(k0) do { \
    ra0 = *(const float4*)(Ab + (size_t)arow * 1024 + (k0) + ac4 * 4); \
    ra1 = *(const float4*)(Ab + (size_t)(arow + 64) * 1024 + (k0) + ac4 * 4); \
    rwh = *(const uint4*)(WhB + (size_t)(((k0) >> 1) + kp) * 1024 + c4 * 4); \
    rwl = *(const uint4*)(WlB + (size_t)(((k0) >> 1) + kp) * 1024 + c4 * 4); \
} while (0)
#define G_STS(pb) do { \
    uint32_t h_, l_; \
    sp(ra0.x, ra0.y, h_, l_); Ah[pb][2*ac4][arow] = h_;      Al[pb][2*ac4][arow] = l_; \
    sp(ra0.z, ra0.w, h_, l_); Ah[pb][2*ac4+1][arow] = h_;    Al[pb][2*ac4+1][arow] = l_; \
    sp(ra1.x, ra1.y, h_, l_); Ah[pb][2*ac4][arow+64] = h_;   Al[pb][2*ac4][arow+64] = l_; \
    sp(ra1.z, ra1.w, h_, l_); Ah[pb][2*ac4+1][arow+64] = h_; Al[pb][2*ac4+1][arow+64] = l_; \
    *(uint4*)&Wh[pb][kp][c4 * 4] = rwh; \
    *(uint4*)&Wl[pb][kp][c4 * 4] = rwl; \
} while (0)

    G_LOAD(0);
    G_STS(0);
    __syncthreads();
    int p = 0;

    for (int k0 = 0; k0 < 1024; k0 += 16) {
        if (k0 + 16 < 1024) G_LOAD(k0 + 16);

        uint32_t af[2][8];
#pragma unroll
        for (int mi = 0; mi < 2; mi++) {
            int mb = wm + mi * 16;
            af[mi][0] = Ah[p][t][mb+g];   af[mi][1] = Ah[p][t][mb+g+8];
            af[mi][2] = Ah[p][t+4][mb+g]; af[mi][3] = Ah[p][t+4][mb+g+8];
            af[mi][4] = Al[p][t][mb+g];   af[mi][5] = Al[p][t][mb+g+8];
            af[mi][6] = Al[p][t+4][mb+g]; af[mi][7] = Al[p][t+4][mb+g+8];
        }
#pragma unroll
        for (int n = 0; n < 8; n++) {
            uint32_t b0h = Wh[p][t][wn+n*8+g], b1h = Wh[p][t+4][wn+n*8+g];
            uint32_t b0l = Wl[p][t][wn+n*8+g], b1l = Wl[p][t+4][wn+n*8+g];
#pragma unroll
            for (int mi = 0; mi < 2; mi++) {
                mma16(acc[mi][n], af[mi][0], af[mi][1], af[mi][2], af[mi][3], b0h, b1h);
                mma16(acc[mi][n], af[mi][4], af[mi][5], af[mi][6], af[mi][7], b0h, b1h);
                mma16(acc[mi][n], af[mi][0], af[mi][1], af[mi][2], af[mi][3], b0l, b1l);
            }
        }
        if (k0 + 16 < 1024) G_STS(p ^ 1);
        __syncthreads();
        p ^= 1;
    }

#pragma unroll
    for (int mi = 0; mi < 2; mi++) {
        int row0 = blockIdx.y * 128 + wm + mi * 16 + g;
#pragma unroll
        for (int n = 0; n < 8; n++) {
            int col = blockIdx.x * 128 + wn + n * 8 + 2 * t;
            float2 bv = *(const float2*)(bias + col);
            *(float2*)(C + (size_t)row0 * 1024 + col) =
                make_float2(acc[mi][n][0] + bv.x, acc[mi][n][1] + bv.y);
            *(float2*)(C + (size_t)(row0 + 8) * 1024 + col) =
                make_float2(acc[mi][n][2] + bv.x, acc[mi][n][3] + bv.y);
        }
    }
}

// ---------------------------------------------------------------------------
// Flash: Br=128, Bc=64, launch_bounds(256,2). K/V staging is now a pure
// LDG.128 -> STS.128 copy of pre-converted tiles (zero conversion ALU).
// Arithmetic identical to round 14 (rel_err must stay 1.2177e-4).
// ---------------------------------------------------------------------------
__global__ void __launch_bounds__(256, 2) flash_kernel(
    const uint32_t* __restrict__ Kt, const uint32_t* __restrict__ V2,
    const float* __restrict__ bm, float* __restrict__ ctx)
{
    __shared__ uint32_t Kp[64 * 72];
    __shared__ uint32_t Vhl[32 * 136];

    const int tid = threadIdx.x, lane = tid & 31, wid = tid >> 5;
    const int g = lane >> 2, t = lane & 3;
    const int wrow = wid * 16;
    const int h = blockIdx.x, q0 = blockIdx.y * 128, b = blockIdx.z;
    const int bh = b * HEADS + h;

    const float* Qg = g_Q + ((size_t)b * NN + q0) * HIDDEN + h * DKH;
    const uint32_t* Ktg = Kt + (size_t)bh * NN * 64;
    const uint32_t* V2g = V2 + (size_t)bh * (NN / 2) * 128;

    const float L2E = 1.44269504088896340736f;
    const float QSC = 0.125f * L2E;

    uint32_t qa[8][4];
#pragma unroll
    for (int kb = 0; kb < 8; kb++) {
        qa[kb][0] = f2tf(__ldg(Qg + (size_t)(wrow+g)  *HIDDEN + kb*8 + t)   * QSC);
        qa[kb][1] = f2tf(__ldg(Qg + (size_t)(wrow+g+8)*HIDDEN + kb*8 + t)   * QSC);
        qa[kb][2] = f2tf(__ldg(Qg + (size_t)(wrow+g)  *HIDDEN + kb*8 + t+4) * QSC);
        qa[kb][3] = f2tf(__ldg(Qg + (size_t)(wrow+g+8)*HIDDEN + kb*8 + t+4) * QSC);
    }

    float Oa[8][4];
#pragma unroll
    for (int n = 0; n < 8; n++)
#pragma unroll
        for (int j = 0; j < 4; j++) Oa[n][j] = 0.f;
    float m0 = -1e30f, m1 = -1e30f, l0 = 0.f, l1 = 0.f;

    const float* bmB = bm + ((size_t)b * NN + q0 + wrow) * NN;

    const int kkey = tid >> 3, kkb = tid & 7;
    const int vrp  = tid >> 4, vdq = tid & 15;

    for (int kt = 0; kt < NN / 64; kt++) {
        const int k0 = kt * 64;
        __syncthreads();

        // K tile: pure copy (pre-permuted tf32)
#pragma unroll
        for (int i = 0; i < 2; i++) {
            int key = kkey + i * 32;
            const uint32_t* kr = Ktg + (size_t)(k0 + key) * 64 + kkb * 8;
            uint4 ua = *(const uint4*)kr;
            uint4 ub = *(const uint4*)(kr + 4);
            uint32_t* d = &Kp[key * 72 + kkb * 8];
            *(uint4*)d       = ua;
            *(uint4*)(d + 4) = ub;
        }
        // V tile: pure copy (pre-split bf16 pairs)
#pragma unroll
        for (int i = 0; i < 2; i++) {
            int rp = vrp + i * 16;
            const uint32_t* vr = V2g + (size_t)(k0 / 2 + rp) * 128 + vdq * 8;
            uint4 u0 = *(const uint4*)vr;
            uint4 u1 = *(const uint4*)(vr + 4);
            uint32_t* d = &Vhl[rp * 136 + vdq * 8];
            *(uint4*)d       = u0;
            *(uint4*)(d + 4) = u1;
        }
        __syncthreads();

        float sacc[8][4];
#pragma unroll
        for (int n = 0; n < 8; n++)
#pragma unroll
            for (int j = 0; j < 4; j++) sacc[n][j] = 0.f;
#pragma unroll
        for (int kb = 0; kb < 8; kb++)
#pragma unroll
            for (int n = 0; n < 8; n++) {
                uint2 bb = *(const uint2*)&Kp[(n*8+g) * 72 + kb*8 + 2*t];
                mma8(sacc[n], qa[kb][0], qa[kb][1], qa[kb][2], qa[kb][3], bb.x, bb.y);
            }

        float mx0 = -1e30f, mx1 = -1e30f;
#pragma unroll
        for (int n = 0; n < 8; n++) {
            float2 u = __ldg((const float2*)(bmB + (size_t)g    * NN + k0 + n*8 + 2*t));
            float2 w = __ldg((const float2*)(bmB + (size_t)(g+8)* NN + k0 + n*8 + 2*t));
            sacc[n][0] = fmaf(u.x, L2E, sacc[n][0]);
            sacc[n][1] = fmaf(u.y, L2E, sacc[n][1]);
            sacc[n][2] = fmaf(w.x, L2E, sacc[n][2]);
            sacc[n][3] = fmaf(w.y, L2E, sacc[n][3]);
            mx0 = fmaxf(mx0, fmaxf(sacc[n][0], sacc[n][1]));
            mx1 = fmaxf(mx1, fmaxf(sacc[n][2], sacc[n][3]));
        }
        mx0 = fmaxf(mx0, __shfl_xor_sync(~0u, mx0, 1));
        mx0 = fmaxf(mx0, __shfl_xor_sync(~0u, mx0, 2));
        mx1 = fmaxf(mx1, __shfl_xor_sync(~0u, mx1, 1));
        mx1 = fmaxf(mx1, __shfl_xor_sync(~0u, mx1, 2));
        float mn0 = fmaxf(m0, mx0), mn1 = fmaxf(m1, mx1);
        float c0 = exp2f(m0 - mn0), c1 = exp2f(m1 - mn1);
        float rs0 = 0.f, rs1 = 0.f;
#pragma unroll
        for (int n = 0; n < 8; n++) {
            sacc[n][0] = exp2f(sacc[n][0] - mn0);
            sacc[n][1] = exp2f(sacc[n][1] - mn0);
            sacc[n][2] = exp2f(sacc[n][2] - mn1);
            sacc[n][3] = exp2f(sacc[n][3] - mn1);
            rs0 += sacc[n][0] + sacc[n][1];
            rs1 += sacc[n][2] + sacc[n][3];
        }
        rs0 += __shfl_xor_sync(~0u, rs0, 1); rs0 += __shfl_xor_sync(~0u, rs0, 2);
        rs1 += __shfl_xor_sync(~0u, rs1, 1); rs1 += __shfl_xor_sync(~0u, rs1, 2);
        l0 = l0 * c0 + rs0; l1 = l1 * c1 + rs1;
        m0 = mn0; m1 = mn1;
#pragma unroll
        for (int n = 0; n < 8; n++) {
            Oa[n][0] *= c0; Oa[n][1] *= c0;
            Oa[n][2] *= c1; Oa[n][3] *= c1;
        }

#pragma unroll
        for (int kb = 0; kb < 4; kb++) {
            uint32_t a0h, a0l, a1h, a1l, a2h, a2l, a3h, a3l;
            sp(sacc[2*kb][0],   sacc[2*kb][1],   a0h, a0l);
            sp(sacc[2*kb][2],   sacc[2*kb][3],   a1h, a1l);
            sp(sacc[2*kb+1][0], sacc[2*kb+1][1], a2h, a2l);
            sp(sacc[2*kb+1][2], sacc[2*kb+1][3], a3h, a3l);
#pragma unroll
            for (int n = 0; n < 8; n++) {
                uint2 p0 = *(const uint2*)&Vhl[(kb*8+t)   * 136 + (n*8+g) * 2];
                uint2 p1 = *(const uint2*)&Vhl[(kb*8+t+4) * 136 + (n*8+g) * 2];
                mma16(Oa[n], a0h, a1h, a2h, a3h, p0.x, p1.x);
                mma16(Oa[n], a0l, a1l, a2l, a3l, p0.x, p1.x);
                mma16(Oa[n], a0h, a1h, a2h, a3h, p0.y, p1.y);
            }
        }
    }

    float inv0 = 1.f / l0, inv1 = 1.f / l1;
    float* o0 = ctx + ((size_t)b * NN + q0 + wrow + g) * HIDDEN + h * DKH;
    float* o1 = o0 + (size_t)8 * HIDDEN;
#pragma unroll
    for (int n = 0; n < 8; n++) {
        *(float2*)&o0[n*8 + 2*t] = make_float2(Oa[n][0]*inv0, Oa[n][1]*inv0);
        *(float2*)&o1[n*8 + 2*t] = make_float2(Oa[n][2]*inv1, Oa[n][3]*inv1);
    }
}

extern "C" void kernel_launch(void* const* d_in, const int* in_sizes, int n_in,
                              void* d_out, int out_size)
{
    const float* q    = (const float*)d_in[0];
    const float* k    = (const float*)d_in[1];
    const float* v    = (const float*)d_in[2];
    const float* abia = (const float*)d_in[3];
    const float* amask= (const float*)d_in[4];
    const float* Wq   = (const float*)d_in[5];
    const float* bq   = (const float*)d_in[6];
    const float* Wk   = (const float*)d_in[7];
    const float* bk   = (const float*)d_in[8];
    const float* Wv   = (const float*)d_in[9];
    const float* bv   = (const float*)d_in[10];
    const float* Wo   = (const float*)d_in[11];
    const float* bo   = (const float*)d_in[12];
    float* out = (float*)d_out;

    float *Qp, *Kp_, *Vp, *Cp, *BMp;
    uint32_t *WH, *WL, *KT, *V2;
    cudaGetSymbolAddress((void**)&Qp, g_Q);
    cudaGetSymbolAddress((void**)&Kp_, g_K);
    cudaGetSymbolAddress((void**)&Vp, g_V);
    cudaGetSymbolAddress((void**)&Cp, g_C);
    cudaGetSymbolAddress((void**)&BMp, g_BM);
    cudaGetSymbolAddress((void**)&WH, g_Wh);
    cudaGetSymbolAddress((void**)&WL, g_Wl);
    cudaGetSymbolAddress((void**)&KT, g_Kt);
    cudaGetSymbolAddress((void**)&V2, g_V2);

    split_w_kernel<<<dim3(2048, 4), 256>>>(Wq, Wk, Wv, Wo, WH, WL);
    add_bm_kernel<<<8192, 256>>>(abia, amask, BMp);

    // batched Q/K/V projections (z = 0,1,2 -> W slices 0,1,2)
    dim3 gb3(HIDDEN / 128, ROWS / 128, 3);   // (8, 32, 3)
    gemm_bf3_kernel<<<gb3, 256>>>(q, k, v, WH, WL, bq, bk, bv, Qp, Kp_, Vp);

    // pre-convert K/V into flash-ready formats (bit-identical conversions)
    conv_k_kernel<<<dim3(64, 32), 256>>>(KT);
    conv_v_kernel<<<dim3(64, 32), 256>>>(V2);

    dim3 gf(HEADS, NN / 128, BB);            // (16, 16, 2)
    flash_kernel<<<gf, 256>>>(KT, V2, BMp, Cp);

    // O projection (z = 0 -> W slice 3 via offset base)
    dim3 gb1(HIDDEN / 128, ROWS / 128, 1);
    gemm_bf3_kernel<<<gb1, 256>>>(Cp, Cp, Cp,
                                  WH + 1572864u, WL + 1572864u,
                                  bo, bo, bo, out, out, out);
}

// round 16
// speedup vs baseline: 1.3410x; 1.0060x over previous
#include <cuda_runtime.h>
#include <cstdint>

#define HIDDEN 1024
#define HEADS  16
#define DKH    64
#define BB     2
#define NN     2048
#define ROWS   (BB*NN)

__device__ float g_Q[ROWS * HIDDEN];
__device__ float g_K[ROWS * HIDDEN];
__device__ float g_V[ROWS * HIDDEN];
__device__ float g_C[ROWS * HIDDEN];
__device__ float g_BM[(size_t)BB * NN * NN];      // bias + mask (33.5 MB)
// flash-ready K: [bh(32)][key(2048)][64 u32]  (tf32, permuted slot order)
__device__ uint32_t g_Kt[ROWS * HIDDEN];
// flash-ready V: [bh(32)][rp(1024)][128 u32]  (bf16 (h,l) interleaved pairs)
__device__ uint32_t g_V2[ROWS * HIDDEN];
// K-major bf16-split weights: [4 mats][512 kpairs][1024 n] u32 (h and l)
__device__ uint32_t g_Wh[4u * 512u * 1024u];
__device__ uint32_t g_Wl[4u * 512u * 1024u];

__device__ __forceinline__ uint32_t f2tf(float x) {
    uint32_t u; asm("cvt.rna.tf32.f32 %0, %1;" : "=r"(u) : "f"(x)); return u;
}
__device__ __forceinline__ uint32_t pk(float a, float b) {
    uint32_t r; asm("cvt.rn.bf16x2.f32 %0, %1, %2;" : "=r"(r) : "f"(b), "f"(a)); return r;
}
__device__ __forceinline__ float blo(uint32_t u) { return __uint_as_float(u << 16); }
__device__ __forceinline__ float bhi(uint32_t u) { return __uint_as_float(u & 0xffff0000u); }
__device__ __forceinline__ void sp(float f0, float f1, uint32_t& h, uint32_t& l) {
    h = pk(f0, f1);
    l = pk(f0 - blo(h), f1 - bhi(h));
}
__device__ __forceinline__ uint32_t smem_u32(const void* p) {
    uint32_t a;
    asm("{ .reg .u64 t; cvta.to.shared.u64 t, %1; cvt.u32.u64 %0, t; }" : "=r"(a) : "l"(p));
    return a;
}
__device__ __forceinline__ void cp16(uint32_t dst, const void* src) {
    asm volatile("cp.async.ca.shared.global [%0], [%1], 16;"
                 :: "r"(dst), "l"(src) : "memory");
}
__device__ __forceinline__ void mma8(float* d, uint32_t a0, uint32_t a1,
    uint32_t a2, uint32_t a3, uint32_t b0, uint32_t b1) {
    asm volatile("mma.sync.aligned.m16n8k8.row.col.f32.tf32.tf32.f32 "
        "{%0,%1,%2,%3},{%4,%5,%6,%7},{%8,%9},{%0,%1,%2,%3};"
        : "+f"(d[0]), "+f"(d[1]), "+f"(d[2]), "+f"(d[3])
        : "r"(a0), "r"(a1), "r"(a2), "r"(a3), "r"(b0), "r"(b1));
}
__device__ __forceinline__ void mma16(float* d, uint32_t a0, uint32_t a1,
    uint32_t a2, uint32_t a3, uint32_t b0, uint32_t b1) {
    asm volatile("mma.sync.aligned.m16n8k16.row.col.f32.bf16.bf16.f32 "
        "{%0,%1,%2,%3},{%4,%5,%6,%7},{%8,%9},{%0,%1,%2,%3};"
        : "+f"(d[0]), "+f"(d[1]), "+f"(d[2]), "+f"(d[3])
        : "r"(a0), "r"(a1), "r"(a2), "r"(a3), "r"(b0), "r"(b1));
}

// ---------------------------------------------------------------------------
__global__ void add_bm_kernel(const float* __restrict__ a,
                              const float* __restrict__ m,
                              float* __restrict__ o)
{
    int i = blockIdx.x * 256 + threadIdx.x;
    float4 x = ((const float4*)a)[i];
    float4 y = ((const float4*)m)[i];
    x.x += y.x; x.y += y.y; x.z += y.z; x.w += y.w;
    ((float4*)o)[i] = x;
}

__global__ void split_w_kernel(
    const float* __restrict__ W0, const float* __restrict__ W1,
    const float* __restrict__ W2, const float* __restrict__ W3,
    uint32_t* __restrict__ outH, uint32_t* __restrict__ outL)
{
    const float* W = (blockIdx.y == 0) ? W0 : (blockIdx.y == 1) ? W1
                   : (blockIdx.y == 2) ? W2 : W3;
    uint32_t* oh = outH + (size_t)blockIdx.y * 524288u;
    uint32_t* ol = outL + (size_t)blockIdx.y * 524288u;
    int idx = blockIdx.x * 256 + threadIdx.x;
    int kp = idx >> 10, n = idx & 1023;
    float w0 = W[(size_t)(2 * kp) * 1024 + n];
    float w1 = W[(size_t)(2 * kp + 1) * 1024 + n];
    uint32_t h, l;
    sp(w0, w1, h, l);
    oh[idx] = h; ol[idx] = l;
}

__global__ void conv_k_kernel(uint32_t* __restrict__ out)
{
    const int bh = blockIdx.y;
    const int b = bh >> 4, h = bh & 15;
    int i = blockIdx.x * 256 + threadIdx.x;
    int key = i >> 3, kkb = i & 7;
    const float* src = g_K + ((size_t)(b * NN + key)) * HIDDEN + h * DKH + kkb * 8;
    float4 fa = *(const float4*)src;
    float4 fb = *(const float4*)(src + 4);
    uint32_t* dst = out + ((size_t)bh * NN + key) * 64 + kkb * 8;
    *(uint4*)dst       = make_uint4(f2tf(fa.x), f2tf(fb.x), f2tf(fa.y), f2tf(fb.y));
    *(uint4*)(dst + 4) = make_uint4(f2tf(fa.z), f2tf(fb.z), f2tf(fa.w), f2tf(fb.w));
}

__global__ void conv_v_kernel(uint32_t* __restrict__ out)
{
    const int bh = blockIdx.y;
    const int b = bh >> 4, h = bh & 15;
    int i = blockIdx.x * 256 + threadIdx.x;
    int rp = i >> 4, dq = i & 15;
    const float* v0 = g_V + ((size_t)(b * NN + 2 * rp)) * HIDDEN + h * DKH + dq * 4;
    const float* v1 = v0 + HIDDEN;
    float4 f0 = *(const float4*)v0;
    float4 f1 = *(const float4*)v1;
    uint4 u0, u1;
    sp(f0.x, f1.x, u0.x, u0.y); sp(f0.y, f1.y, u0.z, u0.w);
    sp(f0.z, f1.z, u1.x, u1.y); sp(f0.w, f1.w, u1.z, u1.w);
    uint32_t* dst = out + ((size_t)bh * (NN / 2) + rp) * 128 + dq * 8;
    *(uint4*)dst       = u0;
    *(uint4*)(dst + 4) = u1;
}

// ---------------------------------------------------------------------------
// bf16x3 GEMM — round-12 mainloop (LDG+reg double-buffer). Batched via z.
// ---------------------------------------------------------------------------
__global__ void __launch_bounds__(256, 2) gemm_bf3_kernel(
    const float* __restrict__ A0, const float* __restrict__ A1,
    const float* __restrict__ A2,
    const uint32_t* __restrict__ WhG, const uint32_t* __restrict__ WlG,
    const float* __restrict__ b0, const float* __restrict__ b1,
    const float* __restrict__ b2,
    float* __restrict__ C0, float* __restrict__ C1, float* __restrict__ C2)
{
    __shared__ uint32_t Ah[2][8][136], Al[2][8][136], Wh[2][8][136], Wl[2][8][136];
    const int tid = threadIdx.x, lane = tid & 31, wid = tid >> 5;
    const int g = lane >> 2, t = lane & 3;
    const int wm = (wid & 3) * 32, wn = (wid >> 2) * 64;
    const int z = blockIdx.z;

    const float* A    = (z == 0) ? A0 : (z == 1) ? A1 : A2;
    const float* bias = (z == 0) ? b0 : (z == 1) ? b1 : b2;
    float*       C    = (z == 0) ? C0 : (z == 1) ? C1 : C2;

    const float* Ab = A + (size_t)blockIdx.y * 128 * 1024;
    const uint32_t* WhB = WhG + (size_t)z * 524288u + blockIdx.x * 128;
    const uint32_t* WlB = WlG + (size_t)z * 524288u + blockIdx.x * 128;

    float acc[2][8][4];
#pragma unroll
    for (int mi = 0; mi < 2; mi++)
#pragma unroll
        for (int n = 0; n < 8; n++)
#pragma unroll
            for (int j = 0; j < 4; j++) acc[mi][n][j] = 0.f;

    const int arow = tid >> 2, ac4 = tid & 3;
    const int kp = tid >> 5, c4 = tid & 31;

    float4 ra0, ra1;
    uint4 rwh, rwl;
#define G_LOAD(k0) do { \
    ra0 = *(const float4*)(Ab + (size_t)arow * 1024 + (k0) + ac4 * 4); \
    ra1 = *(const float4*)(Ab + (size_t)(arow + 64) * 1024 + (k0) + ac4 * 4); \
    rwh = *(const uint4*)(WhB + (size_t)(((k0) >> 1) + kp) * 1024 + c4 * 4); \
    rwl = *(const uint4*)(WlB + (size_t)(((k0) >> 1) + kp) * 1024 + c4 * 4); \
} while (0)
#define G_STS(pb) do { \
    uint32_t h_, l_; \
    sp(ra0.x, ra0.y, h_, l_); Ah[pb][2*ac4][arow] = h_;      Al[pb][2*ac4][arow] = l_; \
    sp(ra0.z, ra0.w, h_, l_); Ah[pb][2*ac4+1][arow] = h_;    Al[pb][2*ac4+1][arow] = l_; \
    sp(ra1.x, ra1.y, h_, l_); Ah[pb][2*ac4][arow+64] = h_;   Al[pb][2*ac4][arow+64] = l_; \
    sp(ra1.z, ra1.w, h_, l_); Ah[pb][2*ac4+1][arow+64] = h_; Al[pb][2*ac4+1][arow+64] = l_; \
    *(uint4*)&Wh[pb][kp][c4 * 4] = rwh; \
    *(uint4*)&Wl[pb][kp][c4 * 4] = rwl; \
} while (0)

    G_LOAD(0);
    G_STS(0);
    __syncthreads();
    int p = 0;

    for (int k0 = 0; k0 < 1024; k0 += 16) {
        if (k0 + 16 < 1024) G_LOAD(k0 + 16);

        uint32_t af[2][8];
#pragma unroll
        for (int mi = 0; mi < 2; mi++) {
            int mb = wm + mi * 16;
            af[mi][0] = Ah[p][t][mb+g];   af[mi][1] = Ah[p][t][mb+g+8];
            af[mi][2] = Ah[p][t+4][mb+g]; af[mi][3] = Ah[p][t+4][mb+g+8];
            af[mi][4] = Al[p][t][mb+g];   af[mi][5] = Al[p][t][mb+g+8];
            af[mi][6] = Al[p][t+4][mb+g]; af[mi][7] = Al[p][t+4][mb+g+8];
        }
#pragma unroll
        for (int n = 0; n < 8; n++) {
            uint32_t b0h = Wh[p][t][wn+n*8+g], b1h = Wh[p][t+4][wn+n*8+g];
            uint32_t b0l = Wl[p][t][wn+n*8+g], b1l = Wl[p][t+4][wn+n*8+g];
#pragma unroll
            for (int mi = 0; mi < 2; mi++) {
                mma16(acc[mi][n], af[mi][0], af[mi][1], af[mi][2], af[mi][3], b0h, b1h);
                mma16(acc[mi][n], af[mi][4], af[mi][5], af[mi][6], af[mi][7], b0h, b1h);
                mma16(acc[mi][n], af[mi][0], af[mi][1], af[mi][2], af[mi][3], b0l, b1l);
            }
        }
        if (k0 + 16 < 1024) G_STS(p ^ 1);
        __syncthreads();
        p ^= 1;
    }

#pragma unroll
    for (int mi = 0; mi < 2; mi++) {
        int row0 = blockIdx.y * 128 + wm + mi * 16 + g;
#pragma unroll
        for (int n = 0; n < 8; n++) {
            int col = blockIdx.x * 128 + wn + n * 8 + 2 * t;
            float2 bv = *(const float2*)(bias + col);
            *(float2*)(C + (size_t)row0 * 1024 + col) =
                make_float2(acc[mi][n][0] + bv.x, acc[mi][n][1] + bv.y);
            *(float2*)(C + (size_t)(row0 + 8) * 1024 + col) =
                make_float2(acc[mi][n][2] + bv.x, acc[mi][n][3] + bv.y);
        }
    }
}

// ---------------------------------------------------------------------------
// Flash: Br=128, Bc=64, launch_bounds(256,2). Double-buffered smem K/V tiles
// filled by cp.async (pure copies of pre-converted data) — tile kt+1 loads
// fully overlap tile kt compute. Arithmetic identical to round 15.
// smem: 2 x (Kp 64x72 + Vhl 32x136) u32 = 71680 B dynamic.
// ---------------------------------------------------------------------------
#define FKSZ (64 * 72)
#define FVSZ (32 * 136)
#define FBUF (FKSZ + FVSZ)                 // 8960 u32
#define FSM_BYTES (2 * FBUF * 4)           // 71680 B

__global__ void __launch_bounds__(256, 2) flash_kernel(
    const uint32_t* __restrict__ Kt, const uint32_t* __restrict__ V2,
    const float* __restrict__ bm, float* __restrict__ ctx)
{
    extern __shared__ uint32_t smf[];

    const int tid = threadIdx.x, lane = tid & 31, wid = tid >> 5;
    const int g = lane >> 2, t = lane & 3;
    const int wrow = wid * 16;
    const int h = blockIdx.x, q0 = blockIdx.y * 128, b = blockIdx.z;
    const int bh = b * HEADS + h;

    const float* Qg = g_Q + ((size_t)b * NN + q0) * HIDDEN + h * DKH;
    const uint32_t* Ktg = Kt + (size_t)bh * NN * 64;
    const uint32_t* V2g = V2 + (size_t)bh * (NN / 2) * 128;

    const float L2E = 1.44269504088896340736f;
    const float QSC = 0.125f * L2E;

    uint32_t qa[8][4];
#pragma unroll
    for (int kb = 0; kb < 8; kb++) {
        qa[kb][0] = f2tf(__ldg(Qg + (size_t)(wrow+g)  *HIDDEN + kb*8 + t)   * QSC);
        qa[kb][1] = f2tf(__ldg(Qg + (size_t)(wrow+g+8)*HIDDEN + kb*8 + t)   * QSC);
        qa[kb][2] = f2tf(__ldg(Qg + (size_t)(wrow+g)  *HIDDEN + kb*8 + t+4) * QSC);
        qa[kb][3] = f2tf(__ldg(Qg + (size_t)(wrow+g+8)*HIDDEN + kb*8 + t+4) * QSC);
    }

    float Oa[8][4];
#pragma unroll
    for (int n = 0; n < 8; n++)
#pragma unroll
        for (int j = 0; j < 4; j++) Oa[n][j] = 0.f;
    float m0 = -1e30f, m1 = -1e30f, l0 = 0.f, l1 = 0.f;

    const float* bmB = bm + ((size_t)b * NN + q0 + wrow) * NN;

    const int kkey = tid >> 3, kkb = tid & 7;
    const int vrp  = tid >> 4, vdq = tid & 15;

    // per-thread cp.async smem destinations (fixed per buffer)
    uint32_t kdst[2][2], vdst[2][2];
#pragma unroll
    for (int pb = 0; pb < 2; pb++) {
        uint32_t* Kp = smf + pb * FBUF;
        uint32_t* Vh = Kp + FKSZ;
#pragma unroll
        for (int i = 0; i < 2; i++) {
            kdst[pb][i] = smem_u32(&Kp[(kkey + i * 32) * 72 + kkb * 8]);
            vdst[pb][i] = smem_u32(&Vh[(vrp + i * 16) * 136 + vdq * 8]);
        }
    }
#define F_CP(pb, kt0) do { \
    const int k0_ = (kt0) * 64; \
    _Pragma("unroll") for (int i = 0; i < 2; i++) { \
        const uint32_t* kr = Ktg + (size_t)(k0_ + kkey + i * 32) * 64 + kkb * 8; \
        cp16(kdst[pb][i], kr); \
        cp16(kdst[pb][i] + 16, kr + 4); \
        const uint32_t* vr = V2g + (size_t)(k0_ / 2 + vrp + i * 16) * 128 + vdq * 8; \
        cp16(vdst[pb][i], vr); \
        cp16(vdst[pb][i] + 16, vr + 4); \
    } \
    asm volatile("cp.async.commit_group;" ::: "memory"); \
} while (0)

    F_CP(0, 0);
    asm volatile("cp.async.wait_group 0;" ::: "memory");
    __syncthreads();
    int p = 0;

    for (int kt = 0; kt < NN / 64; kt++) {
        const int k0 = kt * 64;
        if (kt + 1 < NN / 64) F_CP(p ^ 1, kt + 1);   // overlaps compute below

        const uint32_t* Kp  = smf + p * FBUF;
        const uint32_t* Vhl = Kp + FKSZ;

        float sacc[8][4];
#pragma unroll
        for (int n = 0; n < 8; n++)
#pragma unroll
            for (int j = 0; j < 4; j++) sacc[n][j] = 0.f;
#pragma unroll
        for (int kb = 0; kb < 8; kb++)
#pragma unroll
            for (int n = 0; n < 8; n++) {
                uint2 bb = *(const uint2*)&Kp[(n*8+g) * 72 + kb*8 + 2*t];
                mma8(sacc[n], qa[kb][0], qa[kb][1], qa[kb][2], qa[kb][3], bb.x, bb.y);
            }

        float mx0 = -1e30f, mx1 = -1e30f;
#pragma unroll
        for (int n = 0; n < 8; n++) {
            float2 u = __ldg((const float2*)(bmB + (size_t)g    * NN + k0 + n*8 + 2*t));
            float2 w = __ldg((const float2*)(bmB + (size_t)(g+8)* NN + k0 + n*8 + 2*t));
            sacc[n][0] = fmaf(u.x, L2E, sacc[n][0]);
            sacc[n][1] = fmaf(u.y, L2E, sacc[n][1]);
            sacc[n][2] = fmaf(w.x, L2E, sacc[n][2]);
            sacc[n][3] = fmaf(w.y, L2E, sacc[n][3]);
            mx0 = fmaxf(mx0, fmaxf(sacc[n][0], sacc[n][1]));
            mx1 = fmaxf(mx1, fmaxf(sacc[n][2], sacc[n][3]));
        }
        mx0 = fmaxf(mx0, __shfl_xor_sync(~0u, mx0, 1));
        mx0 = fmaxf(mx0, __shfl_xor_sync(~0u, mx0, 2));
        mx1 = fmaxf(mx1, __shfl_xor_sync(~0u, mx1, 1));
        mx1 = fmaxf(mx1, __shfl_xor_sync(~0u, mx1, 2));
        float mn0 = fmaxf(m0, mx0), mn1 = fmaxf(m1, mx1);
        float c0 = exp2f(m0 - mn0), c1 = exp2f(m1 - mn1);
        float rs0 = 0.f, rs1 = 0.f;
#pragma unroll
        for (int n = 0; n < 8; n++) {
            sacc[n][0] = exp2f(sacc[n][0] - mn0);
            sacc[n][1] = exp2f(sacc[n][1] - mn0);
            sacc[n][2] = exp2f(sacc[n][2] - mn1);
            sacc[n][3] = exp2f(sacc[n][3] - mn1);
            rs0 += sacc[n][0] + sacc[n][1];
            rs1 += sacc[n][2] + sacc[n][3];
        }
        rs0 += __shfl_xor_sync(~0u, rs0, 1); rs0 += __shfl_xor_sync(~0u, rs0, 2);
        rs1 += __shfl_xor_sync(~0u, rs1, 1); rs1 += __shfl_xor_sync(~0u, rs1, 2);
        l0 = l0 * c0 + rs0; l1 = l1 * c1 + rs1;
        m0 = mn0; m1 = mn1;
#pragma unroll
        for (int n = 0; n < 8; n++) {
            Oa[n][0] *= c0; Oa[n][1] *= c0;
            Oa[n][2] *= c1; Oa[n][3] *= c1;
        }

#pragma unroll
        for (int kb = 0; kb < 4; kb++) {
            uint32_t a0h, a0l, a1h, a1l, a2h, a2l, a3h, a3l;
            sp(sacc[2*kb][0],   sacc[2*kb][1],   a0h, a0l);
            sp(sacc[2*kb][2],   sacc[2*kb][3],   a1h, a1l);
            sp(sacc[2*kb+1][0], sacc[2*kb+1][1], a2h, a2l);
            sp(sacc[2*kb+1][2], sacc[2*kb+1][3], a3h, a3l);
#pragma unroll
            for (int n = 0; n < 8; n++) {
                uint2 p0 = *(const uint2*)&Vhl[(kb*8+t)   * 136 + (n*8+g) * 2];
                uint2 p1 = *(const uint2*)&Vhl[(kb*8+t+4) * 136 + (n*8+g) * 2];
                mma16(Oa[n], a0h, a1h, a2h, a3h, p0.x, p1.x);
                mma16(Oa[n], a0l, a1l, a2l, a3l, p0.x, p1.x);
                mma16(Oa[n], a0h, a1h, a2h, a3h, p0.y, p1.y);
            }
        }

        if (kt + 1 < NN / 64)
            asm volatile("cp.async.wait_group 0;" ::: "memory");
        __syncthreads();
        p ^= 1;
    }

    float inv0 = 1.f / l0, inv1 = 1.f / l1;
    float* o0 = ctx + ((size_t)b * NN + q0 + wrow + g) * HIDDEN + h * DKH;
    float* o1 = o0 + (size_t)8 * HIDDEN;
#pragma unroll
    for (int n = 0; n < 8; n++) {
        *(float2*)&o0[n*8 + 2*t] = make_float2(Oa[n][0]*inv0, Oa[n][1]*inv0);
        *(float2*)&o1[n*8 + 2*t] = make_float2(Oa[n][2]*inv1, Oa[n][3]*inv1);
    }
}

extern "C" void kernel_launch(void* const* d_in, const int* in_sizes, int n_in,
                              void* d_out, int out_size)
{
    const float* q    = (const float*)d_in[0];
    const float* k    = (const float*)d_in[1];
    const float* v    = (const float*)d_in[2];
    const float* abia = (const float*)d_in[3];
    const float* amask= (const float*)d_in[4];
    const float* Wq   = (const float*)d_in[5];
    const float* bq   = (const float*)d_in[6];
    const float* Wk   = (const float*)d_in[7];
    const float* bk   = (const float*)d_in[8];
    const float* Wv   = (const float*)d_in[9];
    const float* bv   = (const float*)d_in[10];
    const float* Wo   = (const float*)d_in[11];
    const float* bo   = (const float*)d_in[12];
    float* out = (float*)d_out;

    float *Qp, *Kp_, *Vp, *Cp, *BMp;
    uint32_t *WH, *WL, *KT, *V2;
    cudaGetSymbolAddress((void**)&Qp, g_Q);
    cudaGetSymbolAddress((void**)&Kp_, g_K);
    cudaGetSymbolAddress((void**)&Vp, g_V);
    cudaGetSymbolAddress((void**)&Cp, g_C);
    cudaGetSymbolAddress((void**)&BMp, g_BM);
    cudaGetSymbolAddress((void**)&WH, g_Wh);
    cudaGetSymbolAddress((void**)&WL, g_Wl);
    cudaGetSymbolAddress((void**)&KT, g_Kt);
    cudaGetSymbolAddress((void**)&V2, g_V2);

    cudaFuncSetAttribute(flash_kernel,
                         cudaFuncAttributeMaxDynamicSharedMemorySize, FSM_BYTES);

    split_w_kernel<<<dim3(2048, 4), 256>>>(Wq, Wk, Wv, Wo, WH, WL);
    add_bm_kernel<<<8192, 256>>>(abia, amask, BMp);

    // batched Q/K/V projections (z = 0,1,2 -> W slices 0,1,2)
    dim3 gb3(HIDDEN / 128, ROWS / 128, 3);   // (8, 32, 3)
    gemm_bf3_kernel<<<gb3, 256>>>(q, k, v, WH, WL, bq, bk, bv, Qp, Kp_, Vp);

    // pre-convert K/V into flash-ready formats
    conv_k_kernel<<<dim3(64, 32), 256>>>(KT);
    conv_v_kernel<<<dim3(64, 32), 256>>>(V2);

    dim3 gf(HEADS, NN / 128, BB);            // (16, 16, 2)
    flash_kernel<<<gf, 256, FSM_BYTES>>>(KT, V2, BMp, Cp);

    // O projection (z = 0 -> W slice 3 via offset base)
    dim3 gb1(HIDDEN / 128, ROWS / 128, 1);
    gemm_bf3_kernel<<<gb1, 256>>>(Cp, Cp, Cp,
                                  WH + 1572864u, WL + 1572864u,
                                  bo, bo, bo, out, out, out);
}